// round 1
// baseline (speedup 1.0000x reference)
#include <cuda_runtime.h>

// Problem constants
#define BB   8
#define NN   4096
#define DIMK 768
#define DECN 768
#define MTOT (BB * NN)          // 32768

// Scratch (device globals; no allocation allowed)
__device__ float g_q[(size_t)MTOT * DECN];
__device__ float g_k[(size_t)MTOT * DECN];
__device__ float g_v[(size_t)MTOT * DECN];
__device__ float g_gq[BB * DECN];
__device__ float g_gk[BB * DECN];

#define ROWS_PER_BLK 32
#define BLKS_PER_BATCH (NN / ROWS_PER_BLK)   // 128
#define NPART (BB * BLKS_PER_BATCH)          // 1024
__device__ float g_part[(size_t)NPART * DECN];

// ---------------------------------------------------------------------------
// Tiled fp32 GEMM: C[M,N] = A[M,K] * W[K,N]  (both row-major)
// BM=128, BN=64, BK=16, 256 threads, 8x4 per thread.
// Optional kscale (per-k scaling of A, for gk ⊙ v) and addend (for + q).
// ---------------------------------------------------------------------------
#define BM 128
#define BN 64
#define BK 16
#define TM 8
#define TN 4

__device__ __forceinline__ void gemm_body(
    const float* __restrict__ A, const float* __restrict__ W,
    float* __restrict__ C,
    const float* __restrict__ kscale,   // length DIMK or nullptr
    const float* __restrict__ addend)   // [M, DECN] or nullptr
{
    __shared__ float As[BK][BM + 1];
    __shared__ float Ws[BK][BN];

    const int tid = threadIdx.x;
    const int tx  = tid & 15;           // 0..15 -> columns (TN each)
    const int ty  = tid >> 4;           // 0..15 -> rows    (TM each)
    const int m0  = blockIdx.y * BM;
    const int n0  = blockIdx.x * BN;

    float acc[TM][TN];
#pragma unroll
    for (int i = 0; i < TM; i++)
#pragma unroll
        for (int j = 0; j < TN; j++) acc[i][j] = 0.f;

    for (int k0 = 0; k0 < DIMK; k0 += BK) {
        // Load A tile (BM x BK) as float4, store transposed into As
#pragma unroll
        for (int l = 0; l < 2; l++) {
            int s   = tid + l * 256;          // 0..511 float4 slots
            int row = s >> 2;                 // 0..127
            int kq  = (s & 3) * 4;            // 0,4,8,12
            float4 a4 = *reinterpret_cast<const float4*>(
                &A[(size_t)(m0 + row) * DIMK + k0 + kq]);
            if (kscale) {
                a4.x *= kscale[k0 + kq + 0];
                a4.y *= kscale[k0 + kq + 1];
                a4.z *= kscale[k0 + kq + 2];
                a4.w *= kscale[k0 + kq + 3];
            }
            As[kq + 0][row] = a4.x;
            As[kq + 1][row] = a4.y;
            As[kq + 2][row] = a4.z;
            As[kq + 3][row] = a4.w;
        }
        // Load W tile (BK x BN) as float4
        {
            int s  = tid;                     // 256 float4 slots
            int kk = s >> 4;                  // 0..15
            int cq = (s & 15) * 4;            // 0..60
            *reinterpret_cast<float4*>(&Ws[kk][cq]) =
                *reinterpret_cast<const float4*>(
                    &W[(size_t)(k0 + kk) * DECN + n0 + cq]);
        }
        __syncthreads();

#pragma unroll
        for (int kk = 0; kk < BK; kk++) {
            float a[TM];
#pragma unroll
            for (int i = 0; i < TM; i++) a[i] = As[kk][ty * TM + i];
            float4 b4 = *reinterpret_cast<const float4*>(&Ws[kk][tx * TN]);
            float b[TN] = {b4.x, b4.y, b4.z, b4.w};
#pragma unroll
            for (int i = 0; i < TM; i++)
#pragma unroll
                for (int j = 0; j < TN; j++)
                    acc[i][j] = fmaf(a[i], b[j], acc[i][j]);
        }
        __syncthreads();
    }

#pragma unroll
    for (int i = 0; i < TM; i++) {
        const int m = m0 + ty * TM + i;
        const int n = n0 + tx * TN;
        float4 o = make_float4(acc[i][0], acc[i][1], acc[i][2], acc[i][3]);
        if (addend) {
            const float4 q4 = *reinterpret_cast<const float4*>(
                &addend[(size_t)m * DECN + n]);
            o.x += q4.x; o.y += q4.y; o.z += q4.z; o.w += q4.w;
        }
        *reinterpret_cast<float4*>(&C[(size_t)m * DECN + n]) = o;
    }
}

// q / k / v projections (z selects weight + destination)
__global__ __launch_bounds__(256) void gemm_qkv(
    const float* __restrict__ X,
    const float* __restrict__ Wq,
    const float* __restrict__ Wk,
    const float* __restrict__ Wv)
{
    const float* W;
    float* C;
    if (blockIdx.z == 0)      { W = Wq; C = g_q; }
    else if (blockIdx.z == 1) { W = Wk; C = g_k; }
    else                      { W = Wv; C = g_v; }
    gemm_body(X, W, C, nullptr, nullptr);
}

// out = (gk ⊙ v) @ Wr + q
__global__ __launch_bounds__(256) void gemm_out(
    const float* __restrict__ Wr, float* __restrict__ out)
{
    const int b = (blockIdx.y * BM) / NN;   // tiles never straddle batches (4096 % 128 == 0)
    gemm_body(g_v, Wr, out, &g_gk[b * DECN], g_q);
}

// ---------------------------------------------------------------------------
// Phase kernel: per-row feature softmax + weighted accumulation.
//   phase 0: val = q[row,d],             t = val*alpha*scale
//   phase 1: val = gq[b,d]*k[row,d],     t = val*beta*scale
// Block handles 32 rows of one batch; 8 warps, 4 rows each (d = lane + 32*i).
// Writes fixed-order block partials -> deterministic.
// ---------------------------------------------------------------------------
#define LOG2E 1.4426950408889634f
#define SCALE 0.03608439182435161f   // 768^-0.5

__global__ __launch_bounds__(256) void phase_kernel(
    const float* __restrict__ coef, int phase)
{
    __shared__ float s_coef[DECN];
    __shared__ float s_g[DECN];
    __shared__ float s_acc[8][DECN];

    const int tid  = threadIdx.x;
    const int lane = tid & 31;
    const int w    = tid >> 5;
    const int blk  = blockIdx.x;                      // 0..1023
    const int b    = blk / BLKS_PER_BATCH;
    const int r0   = b * NN + (blk % BLKS_PER_BATCH) * ROWS_PER_BLK;

    const float* __restrict__ in = (phase == 0) ? g_q : g_k;

    for (int d = tid; d < DECN; d += 256) {
        s_coef[d] = coef[d];
        s_g[d]    = (phase == 0) ? 1.f : g_gq[b * DECN + d];
    }
    __syncthreads();

    float acc[24];
#pragma unroll
    for (int i = 0; i < 24; i++) acc[i] = 0.f;

    for (int rr = w; rr < ROWS_PER_BLK; rr += 8) {
        const float* rp = in + (size_t)(r0 + rr) * DECN;
        float val[24], t[24];
        float m = -1e30f;
#pragma unroll
        for (int i = 0; i < 24; i++) {
            const int d = lane + 32 * i;
            val[i] = rp[d] * s_g[d];
            t[i]   = val[i] * s_coef[d] * SCALE;
            m = fmaxf(m, t[i]);
        }
#pragma unroll
        for (int o = 16; o > 0; o >>= 1)
            m = fmaxf(m, __shfl_xor_sync(0xffffffffu, m, o));
        float sum = 0.f;
#pragma unroll
        for (int i = 0; i < 24; i++) {
            t[i] = exp2f((t[i] - m) * LOG2E);
            sum += t[i];
        }
#pragma unroll
        for (int o = 16; o > 0; o >>= 1)
            sum += __shfl_xor_sync(0xffffffffu, sum, o);
        const float inv = 1.f / sum;
#pragma unroll
        for (int i = 0; i < 24; i++)
            acc[i] = fmaf(val[i] * t[i], inv, acc[i]);
    }

#pragma unroll
    for (int i = 0; i < 24; i++) s_acc[w][lane + 32 * i] = acc[i];
    __syncthreads();

    for (int d = tid; d < DECN; d += 256) {
        float s = 0.f;
#pragma unroll
        for (int ww = 0; ww < 8; ww++) s += s_acc[ww][d];
        g_part[(size_t)blk * DECN + d] = s;
    }
}

// Fixed-order reduction of block partials -> g_gq (phase 0) / g_gk (phase 1)
__global__ void reduce_kernel(int phase)
{
    const int b = blockIdx.x;
    const int d = threadIdx.x;          // blockDim = 768
    float s = 0.f;
    for (int i = 0; i < BLKS_PER_BATCH; i++)
        s += g_part[(size_t)(b * BLKS_PER_BATCH + i) * DECN + d];
    if (phase == 0) g_gq[b * DECN + d] = s;
    else            g_gk[b * DECN + d] = s;
}

// ---------------------------------------------------------------------------
extern "C" void kernel_launch(void* const* d_in, const int* in_sizes, int n_in,
                              void* d_out, int out_size)
{
    const float* x     = (const float*)d_in[0];
    const float* Wq    = (const float*)d_in[1];
    const float* Wk    = (const float*)d_in[2];
    const float* Wv    = (const float*)d_in[3];
    const float* Wr    = (const float*)d_in[4];
    const float* alpha = (const float*)d_in[5];
    const float* beta  = (const float*)d_in[6];
    float* out = (float*)d_out;

    dim3 g_qkv(DECN / BN, MTOT / BM, 3);      // 12 x 256 x 3
    gemm_qkv<<<g_qkv, 256>>>(x, Wq, Wk, Wv);

    phase_kernel<<<NPART, 256>>>(alpha, 0);
    reduce_kernel<<<BB, DECN>>>(0);

    phase_kernel<<<NPART, 256>>>(beta, 1);
    reduce_kernel<<<BB, DECN>>>(1);

    dim3 g_out(DECN / BN, MTOT / BM);          // 12 x 256
    gemm_out<<<g_out, 256>>>(Wr, out);
}

// round 6
// speedup vs baseline: 1.7449x; 1.7449x over previous
#include <cuda_runtime.h>
#include <cuda_bf16.h>
#include <cstdint>

// ---------------------------------------------------------------------------
// Problem constants
// ---------------------------------------------------------------------------
#define BB   8
#define NN   4096
#define DIMK 768
#define MTOT (BB * NN)                   // 32768
#define NELEM ((size_t)MTOT * DIMK)      // 25.2M

// ---------------------------------------------------------------------------
// Scratch (device globals; no allocation allowed)
// ---------------------------------------------------------------------------
__device__ float g_q[NELEM];
__device__ float g_k[NELEM];
__device__ float g_v[NELEM];
__device__ float g_gq[BB * DIMK];
__device__ float g_gk[BB * DIMK];

#define ROWS_PER_BLK 32
#define BLKS_PER_BATCH (NN / ROWS_PER_BLK)   // 128
#define NPART (BB * BLKS_PER_BATCH)          // 1024
__device__ float g_part[(size_t)NPART * DIMK];

// weights, transposed + hi/lo split:  g_wt*[m][n*768+k] = split(W_m[k][n])
__device__ __nv_bfloat16 g_wthi[4][DIMK * DIMK];
__device__ __nv_bfloat16 g_wtlo[4][DIMK * DIMK];

// ---------------------------------------------------------------------------
// Only exotic instruction used anywhere: mma.sync (bf16, fp32 accum)
// ---------------------------------------------------------------------------
#define MMA16816(d, a, b) \
    asm volatile("mma.sync.aligned.m16n8k16.row.col.f32.bf16.bf16.f32 " \
        "{%0,%1,%2,%3},{%4,%5,%6,%7},{%8,%9},{%0,%1,%2,%3};" \
        : "+f"((d)[0]), "+f"((d)[1]), "+f"((d)[2]), "+f"((d)[3]) \
        : "r"((a)[0]), "r"((a)[1]), "r"((a)[2]), "r"((a)[3]), \
          "r"((b)[0]), "r"((b)[1]))

__device__ __forceinline__ uint32_t pack2(__nv_bfloat16 a, __nv_bfloat16 b) {
    return (uint32_t)__bfloat16_as_ushort(a) |
           ((uint32_t)__bfloat16_as_ushort(b) << 16);
}

// ---------------------------------------------------------------------------
// GEMM: C[M,768] = A_f32[M,768] @ (Whi+Wlo)^T (+ addend), A split to hi/lo
// in-kernel (3-product bf16 emulation of fp32 GEMM, error ~2^-16).
// Tile 128x128, K_CHUNK=16, 2-stage LDG->STS double buffer, 256 threads.
// SMEM row layout (per 128-row matrix tile): [hi 16*2B | lo 16*2B | pad 16B]
// stride 80B -> all fragment LDS patterns bank-conflict-free.
// ---------------------------------------------------------------------------
#define KC    16
#define ROWB  80
#define TILB  (128 * ROWB)       // 10240 per matrix per stage
#define STG   (2 * TILB)         // 20480 per stage (A + B)
#define NCH   (DIMK / KC)        // 48 chunks

template<bool SCALED, bool ADD>
__device__ __forceinline__ void gemm_core(
    const float* __restrict__ Asrc,          // [M,768] fp32
    const __nv_bfloat16* __restrict__ Bhi,   // [768,768] bf16, [n][k]
    const __nv_bfloat16* __restrict__ Blo,
    float* __restrict__ C,
    const float* __restrict__ addend,        // [M,768] or unused
    const float* __restrict__ scale)         // gk row [768] or unused
{
    __shared__ __align__(16) char smem[2 * STG];   // 40960
    __shared__ float s_gk[DIMK];

    const int tid  = threadIdx.x;
    const int wid  = tid >> 5;
    const int lane = tid & 31;
    const int m0 = blockIdx.y * 128;
    const int n0 = blockIdx.x * 128;
    const int wm = (wid & 3) * 32;
    const int wn = (wid >> 2) * 64;

    if (SCALED) {
        for (int i = tid; i < DIMK; i += 256) s_gk[i] = scale[i];
        __syncthreads();   // R6 FIX: ldg(0)/ldg(1) below read s_gk across warps
    }

    // staging: thread t loads row r = t/2, k-half kh = t%2 (8 elements)
    const int r  = tid >> 1;
    const int kh = tid & 1;
    const float*         gA  = Asrc + (size_t)(m0 + r) * DIMK + kh * 8;
    const __nv_bfloat16* gBh = Bhi  + (size_t)(n0 + r) * DIMK + kh * 8;
    const __nv_bfloat16* gBl = Blo  + (size_t)(n0 + r) * DIMK + kh * 8;
    const uint32_t sA = (uint32_t)(r * ROWB + kh * 16);   // hi bytes; lo at +32

    float acc[2][8][4];
#pragma unroll
    for (int i = 0; i < 2; i++)
#pragma unroll
        for (int j = 0; j < 8; j++)
#pragma unroll
            for (int l = 0; l < 4; l++) acc[i][j][l] = 0.f;

    float af[8];
    uint4 bhv, blv;

    auto ldg = [&](int c) {
        const float4* p = reinterpret_cast<const float4*>(gA + c * KC);
        float4 x0 = p[0], x1 = p[1];
        af[0] = x0.x; af[1] = x0.y; af[2] = x0.z; af[3] = x0.w;
        af[4] = x1.x; af[5] = x1.y; af[6] = x1.z; af[7] = x1.w;
        if (SCALED) {
            const int kb = c * KC + kh * 8;
#pragma unroll
            for (int i = 0; i < 8; i++) af[i] *= s_gk[kb + i];
        }
        bhv = *reinterpret_cast<const uint4*>(gBh + c * KC);
        blv = *reinterpret_cast<const uint4*>(gBl + c * KC);
    };

    auto sts = [&](int buf) {
        char* base = smem + buf * STG;
        __nv_bfloat16 h[8], l[8];
#pragma unroll
        for (int i = 0; i < 8; i++) {
            h[i] = __float2bfloat16_rn(af[i]);
            l[i] = __float2bfloat16_rn(af[i] - __bfloat162float(h[i]));
        }
        uint4 ph = make_uint4(pack2(h[0], h[1]), pack2(h[2], h[3]),
                              pack2(h[4], h[5]), pack2(h[6], h[7]));
        uint4 pl = make_uint4(pack2(l[0], l[1]), pack2(l[2], l[3]),
                              pack2(l[4], l[5]), pack2(l[6], l[7]));
        *reinterpret_cast<uint4*>(base + sA)              = ph;
        *reinterpret_cast<uint4*>(base + sA + 32)         = pl;
        *reinterpret_cast<uint4*>(base + TILB + sA)       = bhv;
        *reinterpret_cast<uint4*>(base + TILB + sA + 32)  = blv;
    };

    ldg(0);
    sts(0);
    ldg(1);
    __syncthreads();

    for (int c = 0; c < NCH; ++c) {
        const char* SAb = smem + (c & 1) * STG;
        const char* SBb = SAb + TILB;

        // ---- fragment loads (plain LDS, conflict-free) ----
        uint32_t ah[2][4], al[2][4];
#pragma unroll
        for (int mt = 0; mt < 2; ++mt) {
            const int row = wm + mt * 16 + (lane >> 2);
            const char* p = SAb + row * ROWB + (lane & 3) * 4;
            ah[mt][0] = *reinterpret_cast<const uint32_t*>(p);
            ah[mt][1] = *reinterpret_cast<const uint32_t*>(p + 8 * ROWB);
            ah[mt][2] = *reinterpret_cast<const uint32_t*>(p + 16);
            ah[mt][3] = *reinterpret_cast<const uint32_t*>(p + 8 * ROWB + 16);
            al[mt][0] = *reinterpret_cast<const uint32_t*>(p + 32);
            al[mt][1] = *reinterpret_cast<const uint32_t*>(p + 8 * ROWB + 32);
            al[mt][2] = *reinterpret_cast<const uint32_t*>(p + 48);
            al[mt][3] = *reinterpret_cast<const uint32_t*>(p + 8 * ROWB + 48);
        }
        uint32_t bh[8][2], bl[8][2];
#pragma unroll
        for (int nt = 0; nt < 8; ++nt) {
            const int row = wn + nt * 8 + (lane >> 2);
            const char* p = SBb + row * ROWB + (lane & 3) * 4;
            bh[nt][0] = *reinterpret_cast<const uint32_t*>(p);
            bh[nt][1] = *reinterpret_cast<const uint32_t*>(p + 16);
            bl[nt][0] = *reinterpret_cast<const uint32_t*>(p + 32);
            bl[nt][1] = *reinterpret_cast<const uint32_t*>(p + 48);
        }

#pragma unroll
        for (int mt = 0; mt < 2; ++mt)
#pragma unroll
            for (int nt = 0; nt < 8; ++nt) {
                MMA16816(acc[mt][nt], ah[mt], bh[nt]);
                MMA16816(acc[mt][nt], ah[mt], bl[nt]);
                MMA16816(acc[mt][nt], al[mt], bh[nt]);
            }

        __syncthreads();
        if (c < NCH - 1) {
            sts((c + 1) & 1);
            if (c < NCH - 2) ldg(c + 2);
            __syncthreads();
        }
    }

    // ---- epilogue (c-frag: row = lane/4 (+8), cols 2*(lane%4)+{0,1}) ----
    const int g  = lane >> 2;
    const int t2 = (lane & 3) * 2;
#pragma unroll
    for (int mt = 0; mt < 2; ++mt) {
#pragma unroll
        for (int nt = 0; nt < 8; ++nt) {
            const int r0 = m0 + wm + mt * 16 + g;
            const int c0 = n0 + wn + nt * 8 + t2;
            float2 v0 = make_float2(acc[mt][nt][0], acc[mt][nt][1]);
            float2 v1 = make_float2(acc[mt][nt][2], acc[mt][nt][3]);
            if (ADD) {
                const float2 q0 = *reinterpret_cast<const float2*>(
                    addend + (size_t)r0 * DIMK + c0);
                const float2 q1 = *reinterpret_cast<const float2*>(
                    addend + (size_t)(r0 + 8) * DIMK + c0);
                v0.x += q0.x; v0.y += q0.y;
                v1.x += q1.x; v1.y += q1.y;
            }
            *reinterpret_cast<float2*>(C + (size_t)r0 * DIMK + c0) = v0;
            *reinterpret_cast<float2*>(C + (size_t)(r0 + 8) * DIMK + c0) = v1;
        }
    }
}

// q/k/v: A = x (fp32), B = W_z^T split
__global__ __launch_bounds__(256) void gemm_qkv_mma(const float* __restrict__ x)
{
    const int z = blockIdx.z;
    float* C = (z == 0) ? g_q : (z == 1) ? g_k : g_v;
    gemm_core<false, false>(x, g_wthi[z], g_wtlo[z], C, nullptr, nullptr);
}

// out = (gk ⊙ v) @ Wr + q   (gk applied in-kernel per batch)
__global__ __launch_bounds__(256) void gemm_out_mma(float* __restrict__ out)
{
    const int b = (blockIdx.y * 128) / NN;
    gemm_core<true, true>(g_v, g_wthi[3], g_wtlo[3], out, g_q,
                          g_gk + b * DIMK);
}

// ---------------------------------------------------------------------------
// Weight prep: g_wt*[m][n*768+k] = split(W_m[k*768+n])  (plain CUDA)
// ---------------------------------------------------------------------------
__global__ __launch_bounds__(256) void prep_weights(
    const float* __restrict__ W0, const float* __restrict__ W1,
    const float* __restrict__ W2, const float* __restrict__ W3)
{
    const int m = blockIdx.y;
    const float* W = (m == 0) ? W0 : (m == 1) ? W1 : (m == 2) ? W2 : W3;
    const int n = blockIdx.x;                       // 0..767
    __nv_bfloat16* hi = g_wthi[m] + (size_t)n * DIMK;
    __nv_bfloat16* lo = g_wtlo[m] + (size_t)n * DIMK;
    for (int k = threadIdx.x; k < DIMK; k += 256) {
        const float v = W[(size_t)k * DIMK + n];
        const __nv_bfloat16 h = __float2bfloat16_rn(v);
        hi[k] = h;
        lo[k] = __float2bfloat16_rn(v - __bfloat162float(h));
    }
}

// ---------------------------------------------------------------------------
// Phase kernels (validated in R1; deterministic two-stage reductions)
// ---------------------------------------------------------------------------
#define LOG2E 1.4426950408889634f
#define SCALE 0.03608439182435161f   // 768^-0.5

__global__ __launch_bounds__(256) void phase_kernel(
    const float* __restrict__ coef, int phase)
{
    __shared__ float s_coef[DIMK];
    __shared__ float s_g[DIMK];
    __shared__ float s_acc[8][DIMK];

    const int tid  = threadIdx.x;
    const int lane = tid & 31;
    const int w    = tid >> 5;
    const int blk  = blockIdx.x;
    const int b    = blk / BLKS_PER_BATCH;
    const int r0   = b * NN + (blk % BLKS_PER_BATCH) * ROWS_PER_BLK;

    const float* __restrict__ in = (phase == 0) ? g_q : g_k;

    for (int d = tid; d < DIMK; d += 256) {
        s_coef[d] = coef[d];
        s_g[d]    = (phase == 0) ? 1.f : g_gq[b * DIMK + d];
    }
    __syncthreads();

    float acc[24];
#pragma unroll
    for (int i = 0; i < 24; i++) acc[i] = 0.f;

    for (int rr = w; rr < ROWS_PER_BLK; rr += 8) {
        const float* rp = in + (size_t)(r0 + rr) * DIMK;
        float val[24], t[24];
        float m = -1e30f;
#pragma unroll
        for (int i = 0; i < 24; i++) {
            const int d = lane + 32 * i;
            val[i] = rp[d] * s_g[d];
            t[i]   = val[i] * s_coef[d] * SCALE;
            m = fmaxf(m, t[i]);
        }
#pragma unroll
        for (int o = 16; o > 0; o >>= 1)
            m = fmaxf(m, __shfl_xor_sync(0xffffffffu, m, o));
        float sum = 0.f;
#pragma unroll
        for (int i = 0; i < 24; i++) {
            t[i] = exp2f((t[i] - m) * LOG2E);
            sum += t[i];
        }
#pragma unroll
        for (int o = 16; o > 0; o >>= 1)
            sum += __shfl_xor_sync(0xffffffffu, sum, o);
        const float inv = 1.f / sum;
#pragma unroll
        for (int i = 0; i < 24; i++)
            acc[i] = fmaf(val[i] * t[i], inv, acc[i]);
    }

#pragma unroll
    for (int i = 0; i < 24; i++) s_acc[w][lane + 32 * i] = acc[i];
    __syncthreads();

    for (int d = tid; d < DIMK; d += 256) {
        float s = 0.f;
#pragma unroll
        for (int ww = 0; ww < 8; ww++) s += s_acc[ww][d];
        g_part[(size_t)blk * DIMK + d] = s;
    }
}

__global__ void reduce_kernel(int phase)
{
    const int b = blockIdx.x;
    const int d = threadIdx.x;          // blockDim = 768
    float s = 0.f;
    for (int i = 0; i < BLKS_PER_BATCH; i++)
        s += g_part[(size_t)(b * BLKS_PER_BATCH + i) * DIMK + d];
    if (phase == 0) g_gq[b * DIMK + d] = s;
    else            g_gk[b * DIMK + d] = s;
}

// ---------------------------------------------------------------------------
extern "C" void kernel_launch(void* const* d_in, const int* in_sizes, int n_in,
                              void* d_out, int out_size)
{
    const float* x     = (const float*)d_in[0];
    const float* Wq    = (const float*)d_in[1];
    const float* Wk    = (const float*)d_in[2];
    const float* Wv    = (const float*)d_in[3];
    const float* Wr    = (const float*)d_in[4];
    const float* alpha = (const float*)d_in[5];
    const float* beta  = (const float*)d_in[6];
    float* out = (float*)d_out;

    prep_weights<<<dim3(DIMK, 4), 256>>>(Wq, Wk, Wv, Wr);

    dim3 gqkv(DIMK / 128, MTOT / 128, 3);                 // (6, 256, 3)
    gemm_qkv_mma<<<gqkv, 256>>>(x);

    phase_kernel<<<NPART, 256>>>(alpha, 0);
    reduce_kernel<<<BB, DIMK>>>(0);

    phase_kernel<<<NPART, 256>>>(beta, 1);
    reduce_kernel<<<BB, DIMK>>>(1);

    dim3 gout(DIMK / 128, MTOT / 128);                    // (6, 256)
    gemm_out_mma<<<gout, 256>>>(out);
}

// round 7
// speedup vs baseline: 2.2597x; 1.2950x over previous
#include <cuda_runtime.h>
#include <cuda_bf16.h>
#include <cstdint>

// ---------------------------------------------------------------------------
// Problem constants
// ---------------------------------------------------------------------------
#define BB   8
#define NN   4096
#define DIMK 768
#define MTOT (BB * NN)                   // 32768
#define NELEM ((size_t)MTOT * DIMK)      // 25.2M
#define WELEM (DIMK * DIMK)              // 589824

// ---------------------------------------------------------------------------
// Scratch (device globals; no allocation allowed)
// ---------------------------------------------------------------------------
__device__ float g_q[NELEM];
__device__ float g_k[NELEM];
__device__ float g_gq[BB * DIMK];
__device__ float g_gk[BB * DIMK];
__device__ float g_wc[BB * WELEM];               // composed Wv*diag(gk_b)*Wr

#define ROWS_PER_BLK 32
#define BLKS_PER_BATCH (NN / ROWS_PER_BLK)   // 128
#define NPART (BB * BLKS_PER_BATCH)          // 1024
__device__ float g_part[(size_t)NPART * DIMK];

// transposed hi/lo weight splits: wt[0]=Wq^T, wt[1]=Wk^T, wt[2]=Wr^T  ([n][k])
__device__ __nv_bfloat16 g_wthi[3][WELEM];
__device__ __nv_bfloat16 g_wtlo[3][WELEM];
// per-batch composed weight, transposed + split: [b][e][i]
__device__ __nv_bfloat16 g_bchi[BB * WELEM];
__device__ __nv_bfloat16 g_bclo[BB * WELEM];

// ---------------------------------------------------------------------------
// mma.sync (bf16, fp32 accum) — the only exotic instruction used
// ---------------------------------------------------------------------------
#define MMA16816(d, a, b) \
    asm volatile("mma.sync.aligned.m16n8k16.row.col.f32.bf16.bf16.f32 " \
        "{%0,%1,%2,%3},{%4,%5,%6,%7},{%8,%9},{%0,%1,%2,%3};" \
        : "+f"((d)[0]), "+f"((d)[1]), "+f"((d)[2]), "+f"((d)[3]) \
        : "r"((a)[0]), "r"((a)[1]), "r"((a)[2]), "r"((a)[3]), \
          "r"((b)[0]), "r"((b)[1]))

__device__ __forceinline__ uint32_t pack2(__nv_bfloat16 a, __nv_bfloat16 b) {
    return (uint32_t)__bfloat16_as_ushort(a) |
           ((uint32_t)__bfloat16_as_ushort(b) << 16);
}

// ---------------------------------------------------------------------------
// GEMM: C[M,768] = A_f32[M,768] @ (Bhi+Blo)^T (+ addend), A split hi/lo
// in-kernel (3-MMA bf16 emulation, error ~2^-17).
// Tile 128x128, K_CHUNK=16, 2-stage LDG->STS double buffer, 256 threads,
// ONE barrier per chunk; JIT B-fragment loads keep regs ~125 -> 2 CTAs/SM.
// SMEM row stride 80B: all LDS patterns bank-conflict-free.
// ---------------------------------------------------------------------------
#define KC    16
#define ROWB  80
#define TILB  (128 * ROWB)       // 10240 per matrix per stage
#define STG   (2 * TILB)         // 20480 per stage (A + B)
#define NCH   (DIMK / KC)        // 48 chunks

template<bool SCALED, bool ADD>
__device__ __forceinline__ void gemm_core(
    const float* __restrict__ Asrc,          // [M,768] fp32 (row-major)
    const __nv_bfloat16* __restrict__ Bhi,   // [768,768] bf16, [n][k]
    const __nv_bfloat16* __restrict__ Blo,
    float* __restrict__ C,
    const float* __restrict__ addend,        // [M,768] or unused
    const float* __restrict__ scale,         // k-scale row [768] or unused
    int m0)
{
    __shared__ __align__(16) char smem[2 * STG];   // 40960
    __shared__ float s_gk[DIMK];

    const int tid  = threadIdx.x;
    const int wid  = tid >> 5;
    const int lane = tid & 31;
    const int n0 = blockIdx.x * 128;
    const int wm = (wid & 3) * 32;
    const int wn = (wid >> 2) * 64;

    if (SCALED) {
        for (int i = tid; i < DIMK; i += 256) s_gk[i] = scale[i];
        __syncthreads();
    }

    // staging: thread t loads row r = t/2, k-half kh = t%2 (8 elements)
    const int r  = tid >> 1;
    const int kh = tid & 1;
    const float*         gA  = Asrc + (size_t)(m0 + r) * DIMK + kh * 8;
    const __nv_bfloat16* gBh = Bhi  + (size_t)(n0 + r) * DIMK + kh * 8;
    const __nv_bfloat16* gBl = Blo  + (size_t)(n0 + r) * DIMK + kh * 8;
    const uint32_t sA = (uint32_t)(r * ROWB + kh * 16);   // hi bytes; lo at +32

    float acc[2][8][4];
#pragma unroll
    for (int i = 0; i < 2; i++)
#pragma unroll
        for (int j = 0; j < 8; j++)
#pragma unroll
            for (int l = 0; l < 4; l++) acc[i][j][l] = 0.f;

    float af[8];
    uint4 bhv, blv;

    auto ldg = [&](int c) {
        const float4* p = reinterpret_cast<const float4*>(gA + c * KC);
        float4 x0 = p[0], x1 = p[1];
        af[0] = x0.x; af[1] = x0.y; af[2] = x0.z; af[3] = x0.w;
        af[4] = x1.x; af[5] = x1.y; af[6] = x1.z; af[7] = x1.w;
        if (SCALED) {
            const int kb = c * KC + kh * 8;
#pragma unroll
            for (int i = 0; i < 8; i++) af[i] *= s_gk[kb + i];
        }
        bhv = *reinterpret_cast<const uint4*>(gBh + c * KC);
        blv = *reinterpret_cast<const uint4*>(gBl + c * KC);
    };

    auto sts = [&](int buf) {
        char* base = smem + buf * STG;
        __nv_bfloat16 h[8], l[8];
#pragma unroll
        for (int i = 0; i < 8; i++) {
            h[i] = __float2bfloat16_rn(af[i]);
            l[i] = __float2bfloat16_rn(af[i] - __bfloat162float(h[i]));
        }
        uint4 ph = make_uint4(pack2(h[0], h[1]), pack2(h[2], h[3]),
                              pack2(h[4], h[5]), pack2(h[6], h[7]));
        uint4 pl = make_uint4(pack2(l[0], l[1]), pack2(l[2], l[3]),
                              pack2(l[4], l[5]), pack2(l[6], l[7]));
        *reinterpret_cast<uint4*>(base + sA)              = ph;
        *reinterpret_cast<uint4*>(base + sA + 32)         = pl;
        *reinterpret_cast<uint4*>(base + TILB + sA)       = bhv;
        *reinterpret_cast<uint4*>(base + TILB + sA + 32)  = blv;
    };

    ldg(0);
    sts(0);
    ldg(1);
    __syncthreads();

    for (int c = 0; c < NCH; ++c) {
        const char* SAb = smem + (c & 1) * STG;
        const char* SBb = SAb + TILB;

        // A fragments (held across all nt)
        uint32_t ah[2][4], al[2][4];
#pragma unroll
        for (int mt = 0; mt < 2; ++mt) {
            const int row = wm + mt * 16 + (lane >> 2);
            const char* p = SAb + row * ROWB + (lane & 3) * 4;
            ah[mt][0] = *reinterpret_cast<const uint32_t*>(p);
            ah[mt][1] = *reinterpret_cast<const uint32_t*>(p + 8 * ROWB);
            ah[mt][2] = *reinterpret_cast<const uint32_t*>(p + 16);
            ah[mt][3] = *reinterpret_cast<const uint32_t*>(p + 8 * ROWB + 16);
            al[mt][0] = *reinterpret_cast<const uint32_t*>(p + 32);
            al[mt][1] = *reinterpret_cast<const uint32_t*>(p + 8 * ROWB + 32);
            al[mt][2] = *reinterpret_cast<const uint32_t*>(p + 48);
            al[mt][3] = *reinterpret_cast<const uint32_t*>(p + 8 * ROWB + 48);
        }

        // JIT B fragments: short live range -> low reg pressure
#pragma unroll
        for (int nt = 0; nt < 8; ++nt) {
            const int row = wn + nt * 8 + (lane >> 2);
            const char* p = SBb + row * ROWB + (lane & 3) * 4;
            uint32_t bh[2], bl[2];
            bh[0] = *reinterpret_cast<const uint32_t*>(p);
            bh[1] = *reinterpret_cast<const uint32_t*>(p + 16);
            bl[0] = *reinterpret_cast<const uint32_t*>(p + 32);
            bl[1] = *reinterpret_cast<const uint32_t*>(p + 48);
#pragma unroll
            for (int mt = 0; mt < 2; ++mt) {
                MMA16816(acc[mt][nt], ah[mt], bh);
                MMA16816(acc[mt][nt], ah[mt], bl);
                MMA16816(acc[mt][nt], al[mt], bh);
            }
        }

        // write next stage (disjoint buffer), prefetch chunk c+2
        if (c < NCH - 1) {
            sts((c + 1) & 1);
            if (c < NCH - 2) ldg(c + 2);
        }
        __syncthreads();
    }

    // ---- epilogue ----
    const int g  = lane >> 2;
    const int t2 = (lane & 3) * 2;
#pragma unroll
    for (int mt = 0; mt < 2; ++mt) {
#pragma unroll
        for (int nt = 0; nt < 8; ++nt) {
            const int r0 = m0 + wm + mt * 16 + g;
            const int c0 = n0 + wn + nt * 8 + t2;
            float2 v0 = make_float2(acc[mt][nt][0], acc[mt][nt][1]);
            float2 v1 = make_float2(acc[mt][nt][2], acc[mt][nt][3]);
            if (ADD) {
                const float2 q0 = *reinterpret_cast<const float2*>(
                    addend + (size_t)r0 * DIMK + c0);
                const float2 q1 = *reinterpret_cast<const float2*>(
                    addend + (size_t)(r0 + 8) * DIMK + c0);
                v0.x += q0.x; v0.y += q0.y;
                v1.x += q1.x; v1.y += q1.y;
            }
            *reinterpret_cast<float2*>(C + (size_t)r0 * DIMK + c0) = v0;
            *reinterpret_cast<float2*>(C + (size_t)(r0 + 8) * DIMK + c0) = v1;
        }
    }
}

// q = x@Wq
__global__ __launch_bounds__(256, 2) void gemm_q_mma(const float* __restrict__ x)
{
    gemm_core<false, false>(x, g_wthi[0], g_wtlo[0], g_q, nullptr, nullptr,
                            blockIdx.y * 128);
}
// k = x@Wk
__global__ __launch_bounds__(256, 2) void gemm_k_mma(const float* __restrict__ x)
{
    gemm_core<false, false>(x, g_wthi[1], g_wtlo[1], g_k, nullptr, nullptr,
                            blockIdx.y * 128);
}
// Wc_b = (Wv * diag(gk_b)) @ Wr      grid (6, 6, 8)
__global__ __launch_bounds__(256, 2) void gemm_compose(const float* __restrict__ Wv)
{
    const int b = blockIdx.z;
    gemm_core<true, false>(Wv, g_wthi[2], g_wtlo[2], g_wc + (size_t)b * WELEM,
                           nullptr, g_gk + b * DIMK, blockIdx.y * 128);
}
// out_b = x_b @ Wc_b + q_b           grid (6, 256)
__global__ __launch_bounds__(256, 2) void gemm_out_mma(
    const float* __restrict__ x, float* __restrict__ out)
{
    const int m0 = blockIdx.y * 128;
    const int b  = m0 >> 12;                     // 4096 rows per batch
    gemm_core<false, true>(x, g_bchi + (size_t)b * WELEM,
                           g_bclo + (size_t)b * WELEM, out, g_q, nullptr, m0);
}

// ---------------------------------------------------------------------------
// Weight prep: wt[m][n*768+k] = split(W_m[k*768+n])
// ---------------------------------------------------------------------------
__device__ __forceinline__ void prep_one(const float* __restrict__ W, int slot)
{
    const int n = blockIdx.x;                       // 0..767
    __nv_bfloat16* hi = g_wthi[slot] + (size_t)n * DIMK;
    __nv_bfloat16* lo = g_wtlo[slot] + (size_t)n * DIMK;
    for (int k = threadIdx.x; k < DIMK; k += 256) {
        const float v = W[(size_t)k * DIMK + n];
        const __nv_bfloat16 h = __float2bfloat16_rn(v);
        hi[k] = h;
        lo[k] = __float2bfloat16_rn(v - __bfloat162float(h));
    }
}
__global__ __launch_bounds__(256) void prep_qk(
    const float* __restrict__ Wq, const float* __restrict__ Wk)
{
    prep_one(blockIdx.y == 0 ? Wq : Wk, blockIdx.y);
}
__global__ __launch_bounds__(256) void prep_r(const float* __restrict__ Wr)
{
    prep_one(Wr, 2);
}

// transpose + split composed weights: bc[b][e*768+i] = split(g_wc[b][i*768+e])
__global__ void tsplit_wc()
{
    __shared__ float t[32][33];
    const int b  = blockIdx.z;
    const float* W = g_wc + (size_t)b * WELEM;
    __nv_bfloat16* hi = g_bchi + (size_t)b * WELEM;
    __nv_bfloat16* lo = g_bclo + (size_t)b * WELEM;
    const int e0 = blockIdx.x * 32, i0 = blockIdx.y * 32;
    const int tx = threadIdx.x, ty = threadIdx.y;
    t[ty][tx] = W[(size_t)(i0 + ty) * DIMK + e0 + tx];
    __syncthreads();
    const float v = t[tx][ty];                        // W[i0+tx][e0+ty]
    const __nv_bfloat16 h = __float2bfloat16_rn(v);
    hi[(size_t)(e0 + ty) * DIMK + i0 + tx] = h;
    lo[(size_t)(e0 + ty) * DIMK + i0 + tx] =
        __float2bfloat16_rn(v - __bfloat162float(h));
}

// ---------------------------------------------------------------------------
// Phase kernels (validated; deterministic two-stage reductions)
// ---------------------------------------------------------------------------
#define LOG2E 1.4426950408889634f
#define SCALE 0.03608439182435161f   // 768^-0.5

__global__ __launch_bounds__(256) void phase_kernel(
    const float* __restrict__ coef, int phase)
{
    __shared__ float s_coef[DIMK];
    __shared__ float s_g[DIMK];
    __shared__ float s_acc[8][DIMK];

    const int tid  = threadIdx.x;
    const int lane = tid & 31;
    const int w    = tid >> 5;
    const int blk  = blockIdx.x;
    const int b    = blk / BLKS_PER_BATCH;
    const int r0   = b * NN + (blk % BLKS_PER_BATCH) * ROWS_PER_BLK;

    const float* __restrict__ in = (phase == 0) ? g_q : g_k;

    for (int d = tid; d < DIMK; d += 256) {
        s_coef[d] = coef[d];
        s_g[d]    = (phase == 0) ? 1.f : g_gq[b * DIMK + d];
    }
    __syncthreads();

    float acc[24];
#pragma unroll
    for (int i = 0; i < 24; i++) acc[i] = 0.f;

    for (int rr = w; rr < ROWS_PER_BLK; rr += 8) {
        const float* rp = in + (size_t)(r0 + rr) * DIMK;
        float val[24], t[24];
        float m = -1e30f;
#pragma unroll
        for (int i = 0; i < 24; i++) {
            const int d = lane + 32 * i;
            val[i] = rp[d] * s_g[d];
            t[i]   = val[i] * s_coef[d] * SCALE;
            m = fmaxf(m, t[i]);
        }
#pragma unroll
        for (int o = 16; o > 0; o >>= 1)
            m = fmaxf(m, __shfl_xor_sync(0xffffffffu, m, o));
        float sum = 0.f;
#pragma unroll
        for (int i = 0; i < 24; i++) {
            t[i] = exp2f((t[i] - m) * LOG2E);
            sum += t[i];
        }
#pragma unroll
        for (int o = 16; o > 0; o >>= 1)
            sum += __shfl_xor_sync(0xffffffffu, sum, o);
        const float inv = 1.f / sum;
#pragma unroll
        for (int i = 0; i < 24; i++)
            acc[i] = fmaf(val[i] * t[i], inv, acc[i]);
    }

#pragma unroll
    for (int i = 0; i < 24; i++) s_acc[w][lane + 32 * i] = acc[i];
    __syncthreads();

    for (int d = tid; d < DIMK; d += 256) {
        float s = 0.f;
#pragma unroll
        for (int ww = 0; ww < 8; ww++) s += s_acc[ww][d];
        g_part[(size_t)blk * DIMK + d] = s;
    }
}

__global__ void reduce_kernel(int phase)
{
    const int b = blockIdx.x;
    const int d = threadIdx.x;          // blockDim = 768
    float s = 0.f;
    for (int i = 0; i < BLKS_PER_BATCH; i++)
        s += g_part[(size_t)(b * BLKS_PER_BATCH + i) * DIMK + d];
    if (phase == 0) g_gq[b * DIMK + d] = s;
    else            g_gk[b * DIMK + d] = s;
}

// ---------------------------------------------------------------------------
extern "C" void kernel_launch(void* const* d_in, const int* in_sizes, int n_in,
                              void* d_out, int out_size)
{
    const float* x     = (const float*)d_in[0];
    const float* Wq    = (const float*)d_in[1];
    const float* Wk    = (const float*)d_in[2];
    const float* Wv    = (const float*)d_in[3];
    const float* Wr    = (const float*)d_in[4];
    const float* alpha = (const float*)d_in[5];
    const float* beta  = (const float*)d_in[6];
    float* out = (float*)d_out;

    dim3 gg(DIMK / 128, MTOT / 128);                      // (6, 256)

    prep_qk<<<dim3(DIMK, 2), 256>>>(Wq, Wk);              // #1
    prep_r<<<DIMK, 256>>>(Wr);                            // #2
    gemm_q_mma<<<gg, 256>>>(x);                           // #3
    phase_kernel<<<NPART, 256>>>(alpha, 0);               // #4
    reduce_kernel<<<BB, DIMK>>>(0);                       // #5
    gemm_k_mma<<<gg, 256>>>(x);                           // #6  <- ncu -s5 -c1
    phase_kernel<<<NPART, 256>>>(beta, 1);                // #7
    reduce_kernel<<<BB, DIMK>>>(1);                       // #8
    gemm_compose<<<dim3(6, 6, BB), 256>>>(Wv);            // #9
    tsplit_wc<<<dim3(24, 24, BB), dim3(32, 32)>>>();      // #10
    gemm_out_mma<<<gg, 256>>>(x, out);                    // #11
}

// round 8
// speedup vs baseline: 3.1189x; 1.3802x over previous
#include <cuda_runtime.h>
#include <cuda_fp16.h>
#include <cstdint>

// ---------------------------------------------------------------------------
// Problem constants
// ---------------------------------------------------------------------------
#define BB   8
#define NN   4096
#define DIMK 768
#define MTOT (BB * NN)                   // 32768
#define NELEM ((size_t)MTOT * DIMK)      // 25.2M
#define WELEM (DIMK * DIMK)              // 589824

// ---------------------------------------------------------------------------
// Scratch (device globals; no allocation allowed)
// ---------------------------------------------------------------------------
__device__ float g_q[NELEM];
__device__ float g_k[NELEM];
__device__ float g_gq[BB * DIMK];
__device__ float g_gk[BB * DIMK];
__device__ float g_wc[BB * WELEM];               // composed Wv*diag(gk_b)*Wr

#define ROWS_PER_BLK 32
#define BLKS_PER_BATCH (NN / ROWS_PER_BLK)   // 128
#define NPART (BB * BLKS_PER_BATCH)          // 1024
__device__ float g_part[(size_t)NPART * DIMK];

// fp16 transposed weights: wt[0]=Wq^T, wt[1]=Wk^T, wt[2]=Wr^T  ([n][k])
__device__ __half g_wt[3][WELEM];
// per-batch composed (Wq + Wv*diag(gk_b)*Wr), transposed: [b][e][i]
__device__ __half g_bc[BB * WELEM];

// ---------------------------------------------------------------------------
// mma.sync (fp16 in, fp32 accum) — the only exotic instruction used
// ---------------------------------------------------------------------------
#define MMA16816F16(d, a, b) \
    asm volatile("mma.sync.aligned.m16n8k16.row.col.f32.f16.f16.f32 " \
        "{%0,%1,%2,%3},{%4,%5,%6,%7},{%8,%9},{%0,%1,%2,%3};" \
        : "+f"((d)[0]), "+f"((d)[1]), "+f"((d)[2]), "+f"((d)[3]) \
        : "r"((a)[0]), "r"((a)[1]), "r"((a)[2]), "r"((a)[3]), \
          "r"((b)[0]), "r"((b)[1]))

__device__ __forceinline__ uint32_t pack2h(__half a, __half b) {
    return (uint32_t)__half_as_ushort(a) |
           ((uint32_t)__half_as_ushort(b) << 16);
}

// ---------------------------------------------------------------------------
// GEMM: C[M,768] = A_f32[M,768] @ B_h^T   (A split to fp16 hi/lo in-kernel:
// 2-MMA emulation; B single fp16). Error ~2^-11 relative per stage.
// Tile 128x128, K_CHUNK=16, 2-stage LDG->STS double buffer, 256 threads,
// one barrier per chunk. SMEM row stride 80B: all LDS patterns conflict-free.
// ---------------------------------------------------------------------------
#define KC    16
#define ROWB  80
#define TILB  (128 * ROWB)       // 10240 per matrix per stage
#define STG   (2 * TILB)         // 20480 per stage (A + B)
#define NCH   (DIMK / KC)        // 48 chunks

template<bool SCALED>
__device__ __forceinline__ void gemm_core(
    const float* __restrict__ Asrc,          // [M,768] fp32 (row-major)
    const __half* __restrict__ Bsrc,         // [768,768] fp16, [n][k]
    float* __restrict__ C,
    const float* __restrict__ scale,         // k-scale row [768] or unused
    int m0)
{
    __shared__ __align__(16) char smem[2 * STG];   // 40960
    __shared__ float s_gk[DIMK];

    const int tid  = threadIdx.x;
    const int wid  = tid >> 5;
    const int lane = tid & 31;
    const int n0 = blockIdx.x * 128;
    const int wm = (wid & 3) * 32;
    const int wn = (wid >> 2) * 64;

    if (SCALED) {
        for (int i = tid; i < DIMK; i += 256) s_gk[i] = scale[i];
        __syncthreads();   // ldg below reads s_gk across warps
    }

    // staging: thread t loads row r = t/2, k-half kh = t%2 (8 elements)
    const int r  = tid >> 1;
    const int kh = tid & 1;
    const float*  gA = Asrc + (size_t)(m0 + r) * DIMK + kh * 8;
    const __half* gB = Bsrc + (size_t)(n0 + r) * DIMK + kh * 8;
    const uint32_t sA = (uint32_t)(r * ROWB + kh * 16);   // hi; lo at +32

    float acc[2][8][4];
#pragma unroll
    for (int i = 0; i < 2; i++)
#pragma unroll
        for (int j = 0; j < 8; j++)
#pragma unroll
            for (int l = 0; l < 4; l++) acc[i][j][l] = 0.f;

    float af[8];
    uint4 bv;

    auto ldg = [&](int c) {
        const float4* p = reinterpret_cast<const float4*>(gA + c * KC);
        float4 x0 = p[0], x1 = p[1];
        af[0] = x0.x; af[1] = x0.y; af[2] = x0.z; af[3] = x0.w;
        af[4] = x1.x; af[5] = x1.y; af[6] = x1.z; af[7] = x1.w;
        if (SCALED) {
            const int kb = c * KC + kh * 8;
#pragma unroll
            for (int i = 0; i < 8; i++) af[i] *= s_gk[kb + i];
        }
        bv = *reinterpret_cast<const uint4*>(gB + c * KC);
    };

    auto sts = [&](int buf) {
        char* base = smem + buf * STG;
        __half h[8], l[8];
#pragma unroll
        for (int i = 0; i < 8; i++) {
            h[i] = __float2half_rn(af[i]);
            l[i] = __float2half_rn(af[i] - __half2float(h[i]));
        }
        uint4 ph = make_uint4(pack2h(h[0], h[1]), pack2h(h[2], h[3]),
                              pack2h(h[4], h[5]), pack2h(h[6], h[7]));
        uint4 pl = make_uint4(pack2h(l[0], l[1]), pack2h(l[2], l[3]),
                              pack2h(l[4], l[5]), pack2h(l[6], l[7]));
        *reinterpret_cast<uint4*>(base + sA)             = ph;
        *reinterpret_cast<uint4*>(base + sA + 32)        = pl;
        *reinterpret_cast<uint4*>(base + TILB + sA)      = bv;
    };

    ldg(0);
    sts(0);
    ldg(1);
    __syncthreads();

    for (int c = 0; c < NCH; ++c) {
        const char* SAb = smem + (c & 1) * STG;
        const char* SBb = SAb + TILB;

        // A fragments (held across all nt)
        uint32_t ah[2][4], al[2][4];
#pragma unroll
        for (int mt = 0; mt < 2; ++mt) {
            const int row = wm + mt * 16 + (lane >> 2);
            const char* p = SAb + row * ROWB + (lane & 3) * 4;
            ah[mt][0] = *reinterpret_cast<const uint32_t*>(p);
            ah[mt][1] = *reinterpret_cast<const uint32_t*>(p + 8 * ROWB);
            ah[mt][2] = *reinterpret_cast<const uint32_t*>(p + 16);
            ah[mt][3] = *reinterpret_cast<const uint32_t*>(p + 8 * ROWB + 16);
            al[mt][0] = *reinterpret_cast<const uint32_t*>(p + 32);
            al[mt][1] = *reinterpret_cast<const uint32_t*>(p + 8 * ROWB + 32);
            al[mt][2] = *reinterpret_cast<const uint32_t*>(p + 48);
            al[mt][3] = *reinterpret_cast<const uint32_t*>(p + 8 * ROWB + 48);
        }

        // JIT B fragments (single fp16)
#pragma unroll
        for (int nt = 0; nt < 8; ++nt) {
            const int row = wn + nt * 8 + (lane >> 2);
            const char* p = SBb + row * ROWB + (lane & 3) * 4;
            uint32_t b[2];
            b[0] = *reinterpret_cast<const uint32_t*>(p);
            b[1] = *reinterpret_cast<const uint32_t*>(p + 16);
#pragma unroll
            for (int mt = 0; mt < 2; ++mt) {
                MMA16816F16(acc[mt][nt], ah[mt], b);
                MMA16816F16(acc[mt][nt], al[mt], b);
            }
        }

        if (c < NCH - 1) {
            sts((c + 1) & 1);
            if (c < NCH - 2) ldg(c + 2);
        }
        __syncthreads();
    }

    // ---- epilogue ----
    const int g  = lane >> 2;
    const int t2 = (lane & 3) * 2;
#pragma unroll
    for (int mt = 0; mt < 2; ++mt) {
#pragma unroll
        for (int nt = 0; nt < 8; ++nt) {
            const int r0 = m0 + wm + mt * 16 + g;
            const int c0 = n0 + wn + nt * 8 + t2;
            *reinterpret_cast<float2*>(C + (size_t)r0 * DIMK + c0) =
                make_float2(acc[mt][nt][0], acc[mt][nt][1]);
            *reinterpret_cast<float2*>(C + (size_t)(r0 + 8) * DIMK + c0) =
                make_float2(acc[mt][nt][2], acc[mt][nt][3]);
        }
    }
}

// q = x@Wq
__global__ __launch_bounds__(256, 2) void gemm_q_mma(const float* __restrict__ x)
{
    gemm_core<false>(x, g_wt[0], g_q, nullptr, blockIdx.y * 128);
}
// k = x@Wk
__global__ __launch_bounds__(256, 2) void gemm_k_mma(const float* __restrict__ x)
{
    gemm_core<false>(x, g_wt[1], g_k, nullptr, blockIdx.y * 128);
}
// Wc_b = (Wv * diag(gk_b)) @ Wr      grid (6, 6, 8)
__global__ __launch_bounds__(256, 2) void gemm_compose(const float* __restrict__ Wv)
{
    const int b = blockIdx.z;
    gemm_core<true>(Wv, g_wt[2], g_wc + (size_t)b * WELEM,
                    g_gk + b * DIMK, blockIdx.y * 128);
}
// out_b = x_b @ (Wq + Wc_b)          grid (6, 256)
__global__ __launch_bounds__(256, 2) void gemm_out_mma(
    const float* __restrict__ x, float* __restrict__ out)
{
    const int m0 = blockIdx.y * 128;
    const int b  = m0 >> 12;                     // 4096 rows per batch
    gemm_core<false>(x, g_bc + (size_t)b * WELEM, out, nullptr, m0);
}

// ---------------------------------------------------------------------------
// Weight prep: wt[m][n*768+k] = fp16(W_m[k*768+n])
// ---------------------------------------------------------------------------
__device__ __forceinline__ void prep_one(const float* __restrict__ W, int slot)
{
    const int n = blockIdx.x;                       // 0..767
    __half* dst = g_wt[slot] + (size_t)n * DIMK;
    for (int k = threadIdx.x; k < DIMK; k += 256)
        dst[k] = __float2half_rn(W[(size_t)k * DIMK + n]);
}
__global__ __launch_bounds__(256) void prep_qk(
    const float* __restrict__ Wq, const float* __restrict__ Wk)
{
    prep_one(blockIdx.y == 0 ? Wq : Wk, blockIdx.y);
}
__global__ __launch_bounds__(256) void prep_r(const float* __restrict__ Wr)
{
    prep_one(Wr, 2);
}

// transpose + fold Wq: bc[b][e*768+i] = fp16(g_wc[b][i*768+e] + Wq[i*768+e])
__global__ void tsplit_wc(const float* __restrict__ Wq)
{
    __shared__ float t[32][33];
    const int b  = blockIdx.z;
    const float* W = g_wc + (size_t)b * WELEM;
    __half* dst = g_bc + (size_t)b * WELEM;
    const int e0 = blockIdx.x * 32, i0 = blockIdx.y * 32;
    const int tx = threadIdx.x, ty = threadIdx.y;
    const size_t src = (size_t)(i0 + ty) * DIMK + e0 + tx;
    t[ty][tx] = W[src] + Wq[src];
    __syncthreads();
    dst[(size_t)(e0 + ty) * DIMK + i0 + tx] = __float2half_rn(t[tx][ty]);
}

// ---------------------------------------------------------------------------
// Phase kernels (validated; deterministic two-stage reductions)
// ---------------------------------------------------------------------------
#define LOG2E 1.4426950408889634f
#define SCALE 0.03608439182435161f   // 768^-0.5

__global__ __launch_bounds__(256) void phase_kernel(
    const float* __restrict__ coef, int phase)
{
    __shared__ float s_coef[DIMK];
    __shared__ float s_g[DIMK];
    __shared__ float s_acc[8][DIMK];

    const int tid  = threadIdx.x;
    const int lane = tid & 31;
    const int w    = tid >> 5;
    const int blk  = blockIdx.x;
    const int b    = blk / BLKS_PER_BATCH;
    const int r0   = b * NN + (blk % BLKS_PER_BATCH) * ROWS_PER_BLK;

    const float* __restrict__ in = (phase == 0) ? g_q : g_k;

    for (int d = tid; d < DIMK; d += 256) {
        s_coef[d] = coef[d];
        s_g[d]    = (phase == 0) ? 1.f : g_gq[b * DIMK + d];
    }
    __syncthreads();

    float acc[24];
#pragma unroll
    for (int i = 0; i < 24; i++) acc[i] = 0.f;

    for (int rr = w; rr < ROWS_PER_BLK; rr += 8) {
        const float* rp = in + (size_t)(r0 + rr) * DIMK;
        float val[24], t[24];
        float m = -1e30f;
#pragma unroll
        for (int i = 0; i < 24; i++) {
            const int d = lane + 32 * i;
            val[i] = rp[d] * s_g[d];
            t[i]   = val[i] * s_coef[d] * SCALE;
            m = fmaxf(m, t[i]);
        }
#pragma unroll
        for (int o = 16; o > 0; o >>= 1)
            m = fmaxf(m, __shfl_xor_sync(0xffffffffu, m, o));
        float sum = 0.f;
#pragma unroll
        for (int i = 0; i < 24; i++) {
            t[i] = exp2f((t[i] - m) * LOG2E);
            sum += t[i];
        }
#pragma unroll
        for (int o = 16; o > 0; o >>= 1)
            sum += __shfl_xor_sync(0xffffffffu, sum, o);
        const float inv = 1.f / sum;
#pragma unroll
        for (int i = 0; i < 24; i++)
            acc[i] = fmaf(val[i] * t[i], inv, acc[i]);
    }

#pragma unroll
    for (int i = 0; i < 24; i++) s_acc[w][lane + 32 * i] = acc[i];
    __syncthreads();

    for (int d = tid; d < DIMK; d += 256) {
        float s = 0.f;
#pragma unroll
        for (int ww = 0; ww < 8; ww++) s += s_acc[ww][d];
        g_part[(size_t)blk * DIMK + d] = s;
    }
}

__global__ void reduce_kernel(int phase)
{
    const int b = blockIdx.x;
    const int d = threadIdx.x;          // blockDim = 768
    float s = 0.f;
    for (int i = 0; i < BLKS_PER_BATCH; i++)
        s += g_part[(size_t)(b * BLKS_PER_BATCH + i) * DIMK + d];
    if (phase == 0) g_gq[b * DIMK + d] = s;
    else            g_gk[b * DIMK + d] = s;
}

// ---------------------------------------------------------------------------
extern "C" void kernel_launch(void* const* d_in, const int* in_sizes, int n_in,
                              void* d_out, int out_size)
{
    const float* x     = (const float*)d_in[0];
    const float* Wq    = (const float*)d_in[1];
    const float* Wk    = (const float*)d_in[2];
    const float* Wv    = (const float*)d_in[3];
    const float* Wr    = (const float*)d_in[4];
    const float* alpha = (const float*)d_in[5];
    const float* beta  = (const float*)d_in[6];
    float* out = (float*)d_out;

    dim3 gg(DIMK / 128, MTOT / 128);                      // (6, 256)

    prep_qk<<<dim3(DIMK, 2), 256>>>(Wq, Wk);              // #1
    prep_r<<<DIMK, 256>>>(Wr);                            // #2
    gemm_q_mma<<<gg, 256>>>(x);                           // #3
    phase_kernel<<<NPART, 256>>>(alpha, 0);               // #4
    reduce_kernel<<<BB, DIMK>>>(0);                       // #5
    gemm_k_mma<<<gg, 256>>>(x);                           // #6  <- ncu -s5 -c1
    phase_kernel<<<NPART, 256>>>(beta, 1);                // #7
    reduce_kernel<<<BB, DIMK>>>(1);                       // #8
    gemm_compose<<<dim3(6, 6, BB), 256>>>(Wv);            // #9
    tsplit_wc<<<dim3(24, 24, BB), dim3(32, 32)>>>(Wq);    // #10
    gemm_out_mma<<<gg, 256>>>(x, out);                    // #11
}

// round 9
// speedup vs baseline: 4.3595x; 1.3978x over previous
#include <cuda_runtime.h>
#include <cuda_fp16.h>
#include <cstdint>

// ---------------------------------------------------------------------------
// Problem constants
// ---------------------------------------------------------------------------
#define BB   8
#define NN   4096
#define DIMK 768
#define MTOT (BB * NN)                   // 32768
#define NELEM ((size_t)MTOT * DIMK)      // 25.2M
#define WELEM (DIMK * DIMK)              // 589824

// ---------------------------------------------------------------------------
// Scratch (device globals; no allocation allowed)
// ---------------------------------------------------------------------------
__device__ float g_q[NELEM];
__device__ float g_k[NELEM];
__device__ float g_gq[BB * DIMK];
__device__ float g_gk[BB * DIMK];
__device__ float g_wc[BB * WELEM];               // composed Wv*diag(gk_b)*Wr

#define ROWS_PER_BLK 32
#define BLKS_PER_BATCH (NN / ROWS_PER_BLK)   // 128
#define NPART (BB * BLKS_PER_BATCH)          // 1024
__device__ float g_part[(size_t)NPART * DIMK];

__device__ __half g_xh[NELEM];                   // x converted to fp16
// fp16 transposed weights: wt[0]=Wq^T, wt[1]=Wk^T, wt[2]=Wr^T  ([n][k])
__device__ __half g_wt[3][WELEM];
// per-batch composed (Wq + Wv*diag(gk_b)*Wr), transposed: [b][e][i]
__device__ __half g_bc[BB * WELEM];

// ---------------------------------------------------------------------------
// mma.sync (fp16 in, fp32 accum)
// ---------------------------------------------------------------------------
#define MMA16816F16(d, a, b) \
    asm volatile("mma.sync.aligned.m16n8k16.row.col.f32.f16.f16.f32 " \
        "{%0,%1,%2,%3},{%4,%5,%6,%7},{%8,%9},{%0,%1,%2,%3};" \
        : "+f"((d)[0]), "+f"((d)[1]), "+f"((d)[2]), "+f"((d)[3]) \
        : "r"((a)[0]), "r"((a)[1]), "r"((a)[2]), "r"((a)[3]), \
          "r"((b)[0]), "r"((b)[1]))

__device__ __forceinline__ uint32_t pack2h(__half a, __half b) {
    return (uint32_t)__half_as_ushort(a) |
           ((uint32_t)__half_as_ushort(b) << 16);
}

// ===========================================================================
// FAST PATH: pure fp16 GEMM (1 MMA per tile-product), A pre-converted fp16.
// C[M,768] = A_h[M,768] @ B_h^T.  Tile 128x128, K_CHUNK=32, 2-stage
// double buffer, 256 threads, one barrier per chunk.
// SMEM rows 64B data + 16B pad (stride 80B): all patterns conflict-free.
// ===========================================================================
#define KC2   32
#define ROWB2 80
#define TILB2 (128 * ROWB2)      // 10240
#define STG2  (2 * TILB2)        // 20480 per stage (A + B)
#define NCH2  (DIMK / KC2)       // 24 chunks

__device__ __forceinline__ void gemm_f16(
    const __half* __restrict__ Asrc,    // [M,768] fp16 row-major
    const __half* __restrict__ Bsrc,    // [768,768] fp16 [n][k]
    float* __restrict__ C, int m0)
{
    __shared__ __align__(16) char smem[2 * STG2];   // 40960

    const int tid  = threadIdx.x;
    const int wid  = tid >> 5;
    const int lane = tid & 31;
    const int n0 = blockIdx.x * 128;
    const int wm = (wid & 3) * 32;
    const int wn = (wid >> 2) * 64;

    // staging: thread t loads row r = t/2, 32B half hf = t%2
    const int r  = tid >> 1;
    const int hf = tid & 1;
    const __half* gA = Asrc + (size_t)(m0 + r) * DIMK + hf * 16;
    const __half* gB = Bsrc + (size_t)(n0 + r) * DIMK + hf * 16;
    const uint32_t sloc = (uint32_t)(r * ROWB2 + hf * 32);

    float acc[2][8][4];
#pragma unroll
    for (int i = 0; i < 2; i++)
#pragma unroll
        for (int j = 0; j < 8; j++)
#pragma unroll
            for (int l = 0; l < 4; l++) acc[i][j][l] = 0.f;

    uint4 av0, av1, bv0, bv1;
    auto ldg = [&](int c) {
        const uint4* pa = reinterpret_cast<const uint4*>(gA + c * KC2);
        const uint4* pb = reinterpret_cast<const uint4*>(gB + c * KC2);
        av0 = pa[0]; av1 = pa[1];
        bv0 = pb[0]; bv1 = pb[1];
    };
    auto sts = [&](int buf) {
        char* base = smem + buf * STG2;
        *reinterpret_cast<uint4*>(base + sloc)              = av0;
        *reinterpret_cast<uint4*>(base + sloc + 16)         = av1;
        *reinterpret_cast<uint4*>(base + TILB2 + sloc)      = bv0;
        *reinterpret_cast<uint4*>(base + TILB2 + sloc + 16) = bv1;
    };

    ldg(0);
    sts(0);
    ldg(1);
    __syncthreads();

    for (int c = 0; c < NCH2; ++c) {
        const char* SAb = smem + (c & 1) * STG2;
        const char* SBb = SAb + TILB2;

#pragma unroll
        for (int ks = 0; ks < 2; ++ks) {
            const int kb = ks * 32;                 // byte offset of k16 block
            uint32_t a[2][4];
#pragma unroll
            for (int mt = 0; mt < 2; ++mt) {
                const int row = wm + mt * 16 + (lane >> 2);
                const char* p = SAb + row * ROWB2 + kb + (lane & 3) * 4;
                a[mt][0] = *reinterpret_cast<const uint32_t*>(p);
                a[mt][1] = *reinterpret_cast<const uint32_t*>(p + 8 * ROWB2);
                a[mt][2] = *reinterpret_cast<const uint32_t*>(p + 16);
                a[mt][3] = *reinterpret_cast<const uint32_t*>(p + 8 * ROWB2 + 16);
            }
#pragma unroll
            for (int nt = 0; nt < 8; ++nt) {
                const int row = wn + nt * 8 + (lane >> 2);
                const char* p = SBb + row * ROWB2 + kb + (lane & 3) * 4;
                uint32_t b[2];
                b[0] = *reinterpret_cast<const uint32_t*>(p);
                b[1] = *reinterpret_cast<const uint32_t*>(p + 16);
                MMA16816F16(acc[0][nt], a[0], b);
                MMA16816F16(acc[1][nt], a[1], b);
            }
        }

        if (c < NCH2 - 1) {
            sts((c + 1) & 1);
            if (c < NCH2 - 2) ldg(c + 2);
        }
        __syncthreads();
    }

    const int g  = lane >> 2;
    const int t2 = (lane & 3) * 2;
#pragma unroll
    for (int mt = 0; mt < 2; ++mt) {
#pragma unroll
        for (int nt = 0; nt < 8; ++nt) {
            const int r0 = m0 + wm + mt * 16 + g;
            const int c0 = n0 + wn + nt * 8 + t2;
            *reinterpret_cast<float2*>(C + (size_t)r0 * DIMK + c0) =
                make_float2(acc[mt][nt][0], acc[mt][nt][1]);
            *reinterpret_cast<float2*>(C + (size_t)(r0 + 8) * DIMK + c0) =
                make_float2(acc[mt][nt][2], acc[mt][nt][3]);
        }
    }
}

__global__ __launch_bounds__(256, 2) void gemm_q_f16()
{
    gemm_f16(g_xh, g_wt[0], g_q, blockIdx.y * 128);
}
__global__ __launch_bounds__(256, 2) void gemm_k_f16()
{
    gemm_f16(g_xh, g_wt[1], g_k, blockIdx.y * 128);
}
__global__ __launch_bounds__(256, 2) void gemm_out_f16(float* __restrict__ out)
{
    const int m0 = blockIdx.y * 128;
    const int b  = m0 >> 12;                     // 4096 rows per batch
    gemm_f16(g_xh, g_bc + (size_t)b * WELEM, out, m0);
}

// ===========================================================================
// ACCURATE PATH (compose only): A fp32 + k-scale, split to fp16 hi/lo
// in-kernel (2-MMA emulation). K_CHUNK=16. Same structure as R8.
// ===========================================================================
#define KC    16
#define ROWB  80
#define TILB  (128 * ROWB)
#define STG   (2 * TILB)
#define NCH   (DIMK / KC)

__device__ __forceinline__ void gemm_f32a(
    const float* __restrict__ Asrc,
    const __half* __restrict__ Bsrc,
    float* __restrict__ C,
    const float* __restrict__ scale, int m0)
{
    __shared__ __align__(16) char smem[2 * STG];
    __shared__ float s_gk[DIMK];

    const int tid  = threadIdx.x;
    const int wid  = tid >> 5;
    const int lane = tid & 31;
    const int n0 = blockIdx.x * 128;
    const int wm = (wid & 3) * 32;
    const int wn = (wid >> 2) * 64;

    for (int i = tid; i < DIMK; i += 256) s_gk[i] = scale[i];
    __syncthreads();

    const int r  = tid >> 1;
    const int kh = tid & 1;
    const float*  gA = Asrc + (size_t)(m0 + r) * DIMK + kh * 8;
    const __half* gB = Bsrc + (size_t)(n0 + r) * DIMK + kh * 8;
    const uint32_t sA = (uint32_t)(r * ROWB + kh * 16);

    float acc[2][8][4];
#pragma unroll
    for (int i = 0; i < 2; i++)
#pragma unroll
        for (int j = 0; j < 8; j++)
#pragma unroll
            for (int l = 0; l < 4; l++) acc[i][j][l] = 0.f;

    float af[8];
    uint4 bv;
    auto ldg = [&](int c) {
        const float4* p = reinterpret_cast<const float4*>(gA + c * KC);
        float4 x0 = p[0], x1 = p[1];
        af[0] = x0.x; af[1] = x0.y; af[2] = x0.z; af[3] = x0.w;
        af[4] = x1.x; af[5] = x1.y; af[6] = x1.z; af[7] = x1.w;
        const int kb = c * KC + kh * 8;
#pragma unroll
        for (int i = 0; i < 8; i++) af[i] *= s_gk[kb + i];
        bv = *reinterpret_cast<const uint4*>(gB + c * KC);
    };
    auto sts = [&](int buf) {
        char* base = smem + buf * STG;
        __half h[8], l[8];
#pragma unroll
        for (int i = 0; i < 8; i++) {
            h[i] = __float2half_rn(af[i]);
            l[i] = __float2half_rn(af[i] - __half2float(h[i]));
        }
        uint4 ph = make_uint4(pack2h(h[0], h[1]), pack2h(h[2], h[3]),
                              pack2h(h[4], h[5]), pack2h(h[6], h[7]));
        uint4 pl = make_uint4(pack2h(l[0], l[1]), pack2h(l[2], l[3]),
                              pack2h(l[4], l[5]), pack2h(l[6], l[7]));
        *reinterpret_cast<uint4*>(base + sA)        = ph;
        *reinterpret_cast<uint4*>(base + sA + 32)   = pl;
        *reinterpret_cast<uint4*>(base + TILB + sA) = bv;
    };

    ldg(0); sts(0); ldg(1);
    __syncthreads();

    for (int c = 0; c < NCH; ++c) {
        const char* SAb = smem + (c & 1) * STG;
        const char* SBb = SAb + TILB;

        uint32_t ah[2][4], al[2][4];
#pragma unroll
        for (int mt = 0; mt < 2; ++mt) {
            const int row = wm + mt * 16 + (lane >> 2);
            const char* p = SAb + row * ROWB + (lane & 3) * 4;
            ah[mt][0] = *reinterpret_cast<const uint32_t*>(p);
            ah[mt][1] = *reinterpret_cast<const uint32_t*>(p + 8 * ROWB);
            ah[mt][2] = *reinterpret_cast<const uint32_t*>(p + 16);
            ah[mt][3] = *reinterpret_cast<const uint32_t*>(p + 8 * ROWB + 16);
            al[mt][0] = *reinterpret_cast<const uint32_t*>(p + 32);
            al[mt][1] = *reinterpret_cast<const uint32_t*>(p + 8 * ROWB + 32);
            al[mt][2] = *reinterpret_cast<const uint32_t*>(p + 48);
            al[mt][3] = *reinterpret_cast<const uint32_t*>(p + 8 * ROWB + 48);
        }
#pragma unroll
        for (int nt = 0; nt < 8; ++nt) {
            const int row = wn + nt * 8 + (lane >> 2);
            const char* p = SBb + row * ROWB + (lane & 3) * 4;
            uint32_t b[2];
            b[0] = *reinterpret_cast<const uint32_t*>(p);
            b[1] = *reinterpret_cast<const uint32_t*>(p + 16);
#pragma unroll
            for (int mt = 0; mt < 2; ++mt) {
                MMA16816F16(acc[mt][nt], ah[mt], b);
                MMA16816F16(acc[mt][nt], al[mt], b);
            }
        }
        if (c < NCH - 1) {
            sts((c + 1) & 1);
            if (c < NCH - 2) ldg(c + 2);
        }
        __syncthreads();
    }

    const int g  = lane >> 2;
    const int t2 = (lane & 3) * 2;
#pragma unroll
    for (int mt = 0; mt < 2; ++mt) {
#pragma unroll
        for (int nt = 0; nt < 8; ++nt) {
            const int r0 = m0 + wm + mt * 16 + g;
            const int c0 = n0 + wn + nt * 8 + t2;
            *reinterpret_cast<float2*>(C + (size_t)r0 * DIMK + c0) =
                make_float2(acc[mt][nt][0], acc[mt][nt][1]);
            *reinterpret_cast<float2*>(C + (size_t)(r0 + 8) * DIMK + c0) =
                make_float2(acc[mt][nt][2], acc[mt][nt][3]);
        }
    }
}

// Wc_b = (Wv * diag(gk_b)) @ Wr      grid (6, 6, 8)
__global__ __launch_bounds__(256, 2) void gemm_compose(const float* __restrict__ Wv)
{
    const int b = blockIdx.z;
    gemm_f32a(Wv, g_wt[2], g_wc + (size_t)b * WELEM,
              g_gk + b * DIMK, blockIdx.y * 128);
}

// ---------------------------------------------------------------------------
// Prep kernels
// ---------------------------------------------------------------------------
__global__ __launch_bounds__(256) void prep_x(const float* __restrict__ x)
{
    const size_t g = (size_t)blockIdx.x * 256 + threadIdx.x;   // 8 elems
    const float4* sp = reinterpret_cast<const float4*>(x) + g * 2;
    float4 a = sp[0], b = sp[1];
    __half h[8] = {
        __float2half_rn(a.x), __float2half_rn(a.y),
        __float2half_rn(a.z), __float2half_rn(a.w),
        __float2half_rn(b.x), __float2half_rn(b.y),
        __float2half_rn(b.z), __float2half_rn(b.w)};
    reinterpret_cast<uint4*>(g_xh)[g] = *reinterpret_cast<uint4*>(h);
}

__device__ __forceinline__ void prep_one(const float* __restrict__ W, int slot)
{
    const int n = blockIdx.x;
    __half* dst = g_wt[slot] + (size_t)n * DIMK;
    for (int k = threadIdx.x; k < DIMK; k += 256)
        dst[k] = __float2half_rn(W[(size_t)k * DIMK + n]);
}
__global__ __launch_bounds__(256) void prep_qk(
    const float* __restrict__ Wq, const float* __restrict__ Wk)
{
    prep_one(blockIdx.y == 0 ? Wq : Wk, blockIdx.y);
}
__global__ __launch_bounds__(256) void prep_r(const float* __restrict__ Wr)
{
    prep_one(Wr, 2);
}

// transpose + fold Wq: bc[b][e*768+i] = fp16(g_wc[b][i*768+e] + Wq[i*768+e])
__global__ void tsplit_wc(const float* __restrict__ Wq)
{
    __shared__ float t[32][33];
    const int b  = blockIdx.z;
    const float* W = g_wc + (size_t)b * WELEM;
    __half* dst = g_bc + (size_t)b * WELEM;
    const int e0 = blockIdx.x * 32, i0 = blockIdx.y * 32;
    const int tx = threadIdx.x, ty = threadIdx.y;
    const size_t src = (size_t)(i0 + ty) * DIMK + e0 + tx;
    t[ty][tx] = W[src] + Wq[src];
    __syncthreads();
    dst[(size_t)(e0 + ty) * DIMK + i0 + tx] = __float2half_rn(t[tx][ty]);
}

// ---------------------------------------------------------------------------
// Phase kernels (deterministic two-stage reductions); reduced registers:
// only val[24]+acc[24] live; e folded into val (single exp per element).
// ---------------------------------------------------------------------------
#define LOG2E 1.4426950408889634f
#define SCALE 0.03608439182435161f   // 768^-0.5

__global__ __launch_bounds__(256, 2) void phase_kernel(
    const float* __restrict__ coef, int phase)
{
    __shared__ float s_cs[DIMK];          // coef * SCALE
    __shared__ float s_g[DIMK];
    __shared__ float s_acc[8][DIMK];

    const int tid  = threadIdx.x;
    const int lane = tid & 31;
    const int w    = tid >> 5;
    const int blk  = blockIdx.x;
    const int b    = blk / BLKS_PER_BATCH;
    const int r0   = b * NN + (blk % BLKS_PER_BATCH) * ROWS_PER_BLK;

    const float* __restrict__ in = (phase == 0) ? g_q : g_k;

    for (int d = tid; d < DIMK; d += 256) {
        s_cs[d] = coef[d] * SCALE;
        s_g[d]  = (phase == 0) ? 1.f : g_gq[b * DIMK + d];
    }
    __syncthreads();

    float acc[24];
#pragma unroll
    for (int i = 0; i < 24; i++) acc[i] = 0.f;

    for (int rr = w; rr < ROWS_PER_BLK; rr += 8) {
        const float* rp = in + (size_t)(r0 + rr) * DIMK;
        float val[24];
        float m = -1e30f;
#pragma unroll
        for (int i = 0; i < 24; i++) {
            const int d = lane + 32 * i;
            val[i] = rp[d] * s_g[d];
            m = fmaxf(m, val[i] * s_cs[d]);
        }
#pragma unroll
        for (int o = 16; o > 0; o >>= 1)
            m = fmaxf(m, __shfl_xor_sync(0xffffffffu, m, o));
        float sum = 0.f;
#pragma unroll
        for (int i = 0; i < 24; i++) {
            const int d = lane + 32 * i;
            const float e = exp2f((val[i] * s_cs[d] - m) * LOG2E);
            sum += e;
            val[i] *= e;
        }
#pragma unroll
        for (int o = 16; o > 0; o >>= 1)
            sum += __shfl_xor_sync(0xffffffffu, sum, o);
        const float inv = 1.f / sum;
#pragma unroll
        for (int i = 0; i < 24; i++)
            acc[i] = fmaf(val[i], inv, acc[i]);
    }

#pragma unroll
    for (int i = 0; i < 24; i++) s_acc[w][lane + 32 * i] = acc[i];
    __syncthreads();

    for (int d = tid; d < DIMK; d += 256) {
        float s = 0.f;
#pragma unroll
        for (int ww = 0; ww < 8; ww++) s += s_acc[ww][d];
        g_part[(size_t)blk * DIMK + d] = s;
    }
}

// grid (8, 6), block 128: block (b, j) reduces d-range [j*128, j*128+128)
__global__ void reduce_kernel(int phase)
{
    const int b = blockIdx.x;
    const int d = blockIdx.y * 128 + threadIdx.x;
    const float* P = g_part + (size_t)b * BLKS_PER_BATCH * DIMK + d;
    float s0 = 0.f, s1 = 0.f, s2 = 0.f, s3 = 0.f;
#pragma unroll 4
    for (int i = 0; i < BLKS_PER_BATCH; i += 4) {
        s0 += P[(size_t)(i + 0) * DIMK];
        s1 += P[(size_t)(i + 1) * DIMK];
        s2 += P[(size_t)(i + 2) * DIMK];
        s3 += P[(size_t)(i + 3) * DIMK];
    }
    const float s = (s0 + s1) + (s2 + s3);
    if (phase == 0) g_gq[b * DIMK + d] = s;
    else            g_gk[b * DIMK + d] = s;
}

// ---------------------------------------------------------------------------
extern "C" void kernel_launch(void* const* d_in, const int* in_sizes, int n_in,
                              void* d_out, int out_size)
{
    const float* x     = (const float*)d_in[0];
    const float* Wq    = (const float*)d_in[1];
    const float* Wk    = (const float*)d_in[2];
    const float* Wv    = (const float*)d_in[3];
    const float* Wr    = (const float*)d_in[4];
    const float* alpha = (const float*)d_in[5];
    const float* beta  = (const float*)d_in[6];
    float* out = (float*)d_out;

    dim3 gg(DIMK / 128, MTOT / 128);                      // (6, 256)

    prep_x<<<(int)(NELEM / 8 / 256), 256>>>(x);
    prep_qk<<<dim3(DIMK, 2), 256>>>(Wq, Wk);
    prep_r<<<DIMK, 256>>>(Wr);
    gemm_q_f16<<<gg, 256>>>();
    phase_kernel<<<NPART, 256>>>(alpha, 0);
    reduce_kernel<<<dim3(BB, 6), 128>>>(0);
    gemm_k_f16<<<gg, 256>>>();
    phase_kernel<<<NPART, 256>>>(beta, 1);
    reduce_kernel<<<dim3(BB, 6), 128>>>(1);
    gemm_compose<<<dim3(6, 6, BB), 256>>>(Wv);
    tsplit_wc<<<dim3(24, 24, BB), dim3(32, 32)>>>(Wq);
    gemm_out_f16<<<gg, 256>>>(out);
}

// round 11
// speedup vs baseline: 6.8787x; 1.5778x over previous
#include <cuda_runtime.h>
#include <cuda_fp16.h>
#include <cstdint>

// ---------------------------------------------------------------------------
// Problem constants
// ---------------------------------------------------------------------------
#define BB   8
#define NN   4096
#define DIMK 768
#define MTOT (BB * NN)                   // 32768
#define NELEM ((size_t)MTOT * DIMK)      // 25.2M
#define WELEM (DIMK * DIMK)              // 589824
#define NK16  (DIMK / 16)                // 48 k16 steps

// ---------------------------------------------------------------------------
// Scratch (device globals; no allocation allowed)
// ---------------------------------------------------------------------------
__device__ float g_q[NELEM];
__device__ float g_k[NELEM];
__device__ float g_gq[BB * DIMK];
__device__ float g_gk[BB * DIMK];
__device__ float g_wc[BB * WELEM];       // composed Wv*diag(gk_b)*Wr (fp32)

#define ROWS_PER_BLK 32
#define BLKS_PER_BATCH (NN / ROWS_PER_BLK)   // 128
#define NPART (BB * BLKS_PER_BATCH)          // 1024
__device__ float g_part[(size_t)NPART * DIMK];

// Fragment-layout operands (uint4 = 16B per lane per k16 step)
//   A frag: [mblk(16 rows)][s(48)][lane(32)] -> words a0,a1,a2,a3
//   B frag: [npair(16 rows)][s(48)][lane(32)] -> words w0..w3
#define AFRAG_N ((size_t)(MTOT / 16) * NK16 * 32)     // 3.15M uint4
#define BFRAG_N ((size_t)(DIMK / 16) * NK16 * 32)     // 73728 uint4
__device__ uint4 g_xa[AFRAG_N];                  // x in A-frag layout (fp16)
__device__ uint4 g_wf0[BFRAG_N];                 // Wq  B-frag
__device__ uint4 g_wf1[BFRAG_N];                 // Wk  B-frag
__device__ uint4 g_bcf[BB * BFRAG_N];            // (Wq + Wc_b) B-frag
__device__ __half g_wtr[WELEM];                  // Wr^T row-major (compose only)

// ---------------------------------------------------------------------------
// mma.sync (fp16 in, fp32 accum)
// ---------------------------------------------------------------------------
#define MMA16816F16(d, a, b) \
    asm volatile("mma.sync.aligned.m16n8k16.row.col.f32.f16.f16.f32 " \
        "{%0,%1,%2,%3},{%4,%5,%6,%7},{%8,%9},{%0,%1,%2,%3};" \
        : "+f"((d)[0]), "+f"((d)[1]), "+f"((d)[2]), "+f"((d)[3]) \
        : "r"((a)[0]), "r"((a)[1]), "r"((a)[2]), "r"((a)[3]), \
          "r"((b)[0]), "r"((b)[1]))

__device__ __forceinline__ uint32_t pack2h(__half a, __half b) {
    return (uint32_t)__half_as_ushort(a) |
           ((uint32_t)__half_as_ushort(b) << 16);
}
__device__ __forceinline__ uint32_t pack2f(float a, float b) {
    return pack2h(__float2half_rn(a), __float2half_rn(b));
}

// ===========================================================================
// SMEM-FREE fp16 GEMM: C[M,768] = A @ B^T, operands in fragment layout.
// CTA tile 128x128, 8 warps (4m x 2n), warp tile 32x64.
// Per k16 step per warp: 2 A-LDG.128 + 4 B-LDG.128 + 16 HMMA; register
// double buffer, no shared memory, no barriers in the mainloop.
// ===========================================================================
#define STEP32 32                       // uint4 stride between k16 steps
#define BLKOFF (NK16 * 32)              // 1536: uint4 stride between m/n blocks

__device__ __forceinline__ void gemm_frag(
    const uint4* __restrict__ Afrag,
    const uint4* __restrict__ Bfrag,
    float* __restrict__ C, int m0, int n0)
{
    const int tid  = threadIdx.x;
    const int wid  = tid >> 5;
    const int lane = tid & 31;
    const int wm = (wid & 3) * 32;
    const int wn = (wid >> 2) * 64;

    const uint4* pa = Afrag + (size_t)((m0 + wm) >> 4) * BLKOFF + lane;
    const uint4* pb = Bfrag + (size_t)((n0 + wn) >> 4) * BLKOFF + lane;

    float acc[2][8][4];
#pragma unroll
    for (int i = 0; i < 2; i++)
#pragma unroll
        for (int j = 0; j < 8; j++)
#pragma unroll
            for (int l = 0; l < 4; l++) acc[i][j][l] = 0.f;

    uint4 a0[2], a1[2];        // [mt]
    uint4 b0[4], b1[4];        // [npair]

    a0[0] = pa[0]; a0[1] = pa[BLKOFF];
    b0[0] = pb[0];          b0[1] = pb[BLKOFF];
    b0[2] = pb[2 * BLKOFF]; b0[3] = pb[3 * BLKOFF];
    pa += STEP32; pb += STEP32;

    auto step = [&](uint4 (&ac)[2], uint4 (&bc)[4],
                    uint4 (&an)[2], uint4 (&bn)[4], bool pf) {
        if (pf) {
            an[0] = pa[0]; an[1] = pa[BLKOFF];
            bn[0] = pb[0];          bn[1] = pb[BLKOFF];
            bn[2] = pb[2 * BLKOFF]; bn[3] = pb[3 * BLKOFF];
            pa += STEP32; pb += STEP32;
        }
        const uint32_t* am0 = reinterpret_cast<const uint32_t*>(&ac[0]);
        const uint32_t* am1 = reinterpret_cast<const uint32_t*>(&ac[1]);
#pragma unroll
        for (int pr = 0; pr < 4; ++pr) {
            const uint32_t* bw = reinterpret_cast<const uint32_t*>(&bc[pr]);
            MMA16816F16(acc[0][2 * pr],     am0, bw);
            MMA16816F16(acc[1][2 * pr],     am1, bw);
            MMA16816F16(acc[0][2 * pr + 1], am0, bw + 2);
            MMA16816F16(acc[1][2 * pr + 1], am1, bw + 2);
        }
    };

#pragma unroll 1
    for (int s = 0; s < NK16; s += 2) {
        step(a0, b0, a1, b1, true);              // compute s, prefetch s+1
        step(a1, b1, a0, b0, s + 2 < NK16);      // compute s+1, prefetch s+2
    }

    const int g  = lane >> 2;
    const int t2 = (lane & 3) * 2;
#pragma unroll
    for (int mt = 0; mt < 2; ++mt) {
#pragma unroll
        for (int nt = 0; nt < 8; ++nt) {
            const int r0 = m0 + wm + mt * 16 + g;
            const int c0 = n0 + wn + nt * 8 + t2;
            *reinterpret_cast<float2*>(C + (size_t)r0 * DIMK + c0) =
                make_float2(acc[mt][nt][0], acc[mt][nt][1]);
            *reinterpret_cast<float2*>(C + (size_t)(r0 + 8) * DIMK + c0) =
                make_float2(acc[mt][nt][2], acc[mt][nt][3]);
        }
    }
}

// fused q|k: grid (12, 256); x-halves select weight + destination
__global__ __launch_bounds__(256, 2) void gemm_qk()
{
    const int bx = blockIdx.x;
    const bool sel = bx >= 6;
    gemm_frag(g_xa, sel ? g_wf1 : g_wf0, sel ? g_k : g_q,
              blockIdx.y * 128, (sel ? bx - 6 : bx) * 128);
}
// out_b = x_b @ (Wq + Wc_b)^T : grid (6, 256)
__global__ __launch_bounds__(256, 2) void gemm_out(float* __restrict__ out)
{
    const int m0 = blockIdx.y * 128;
    const int b  = m0 >> 12;
    gemm_frag(g_xa, g_bcf + (size_t)b * BFRAG_N, out, m0, blockIdx.x * 128);
}

// ===========================================================================
// COMPOSE (small, accurate): Wc_b = (Wv * diag(gk_b)) @ Wr, fp32 A split to
// fp16 hi/lo (2-MMA), smem pipeline. grid (6,6,8).
// ===========================================================================
#define KC    16
#define ROWB  80
#define TILB  (128 * ROWB)
#define STG   (2 * TILB)
#define NCH   (DIMK / KC)

__global__ __launch_bounds__(256, 2) void gemm_compose(const float* __restrict__ Wv)
{
    __shared__ __align__(16) char smem[2 * STG];
    __shared__ float s_gk[DIMK];

    const int b = blockIdx.z;
    const float* __restrict__ Asrc = Wv;
    const __half* __restrict__ Bsrc = g_wtr;
    float* __restrict__ C = g_wc + (size_t)b * WELEM;
    const float* __restrict__ scale = g_gk + b * DIMK;
    const int m0 = blockIdx.y * 128;

    const int tid  = threadIdx.x;
    const int wid  = tid >> 5;
    const int lane = tid & 31;
    const int n0 = blockIdx.x * 128;
    const int wm = (wid & 3) * 32;
    const int wn = (wid >> 2) * 64;

    for (int i = tid; i < DIMK; i += 256) s_gk[i] = scale[i];
    __syncthreads();

    const int r  = tid >> 1;
    const int kh = tid & 1;
    const float*  gA = Asrc + (size_t)(m0 + r) * DIMK + kh * 8;
    const __half* gB = Bsrc + (size_t)(n0 + r) * DIMK + kh * 8;
    const uint32_t sA = (uint32_t)(r * ROWB + kh * 16);

    float acc[2][8][4];
#pragma unroll
    for (int i = 0; i < 2; i++)
#pragma unroll
        for (int j = 0; j < 8; j++)
#pragma unroll
            for (int l = 0; l < 4; l++) acc[i][j][l] = 0.f;

    float af[8];
    uint4 bv;
    auto ldg = [&](int c) {
        const float4* p = reinterpret_cast<const float4*>(gA + c * KC);
        float4 x0 = p[0], x1 = p[1];
        af[0] = x0.x; af[1] = x0.y; af[2] = x0.z; af[3] = x0.w;
        af[4] = x1.x; af[5] = x1.y; af[6] = x1.z; af[7] = x1.w;
        const int kb = c * KC + kh * 8;
#pragma unroll
        for (int i = 0; i < 8; i++) af[i] *= s_gk[kb + i];
        bv = *reinterpret_cast<const uint4*>(gB + c * KC);
    };
    auto sts = [&](int buf) {
        char* base = smem + buf * STG;
        __half h[8], l[8];
#pragma unroll
        for (int i = 0; i < 8; i++) {
            h[i] = __float2half_rn(af[i]);
            l[i] = __float2half_rn(af[i] - __half2float(h[i]));
        }
        uint4 ph = make_uint4(pack2h(h[0], h[1]), pack2h(h[2], h[3]),
                              pack2h(h[4], h[5]), pack2h(h[6], h[7]));
        uint4 pl = make_uint4(pack2h(l[0], l[1]), pack2h(l[2], l[3]),
                              pack2h(l[4], l[5]), pack2h(l[6], l[7]));
        *reinterpret_cast<uint4*>(base + sA)        = ph;
        *reinterpret_cast<uint4*>(base + sA + 32)   = pl;
        *reinterpret_cast<uint4*>(base + TILB + sA) = bv;
    };

    ldg(0); sts(0); ldg(1);
    __syncthreads();

    for (int c = 0; c < NCH; ++c) {
        const char* SAb = smem + (c & 1) * STG;
        const char* SBb = SAb + TILB;

        uint32_t ah[2][4], al[2][4];
#pragma unroll
        for (int mt = 0; mt < 2; ++mt) {
            const int row = wm + mt * 16 + (lane >> 2);
            const char* p = SAb + row * ROWB + (lane & 3) * 4;
            ah[mt][0] = *reinterpret_cast<const uint32_t*>(p);
            ah[mt][1] = *reinterpret_cast<const uint32_t*>(p + 8 * ROWB);
            ah[mt][2] = *reinterpret_cast<const uint32_t*>(p + 16);
            ah[mt][3] = *reinterpret_cast<const uint32_t*>(p + 8 * ROWB + 16);
            al[mt][0] = *reinterpret_cast<const uint32_t*>(p + 32);
            al[mt][1] = *reinterpret_cast<const uint32_t*>(p + 8 * ROWB + 32);
            al[mt][2] = *reinterpret_cast<const uint32_t*>(p + 48);
            al[mt][3] = *reinterpret_cast<const uint32_t*>(p + 8 * ROWB + 48);
        }
#pragma unroll
        for (int nt = 0; nt < 8; ++nt) {
            const int row = wn + nt * 8 + (lane >> 2);
            const char* p = SBb + row * ROWB + (lane & 3) * 4;
            uint32_t bq[2];
            bq[0] = *reinterpret_cast<const uint32_t*>(p);
            bq[1] = *reinterpret_cast<const uint32_t*>(p + 16);
#pragma unroll
            for (int mt = 0; mt < 2; ++mt) {
                MMA16816F16(acc[mt][nt], ah[mt], bq);
                MMA16816F16(acc[mt][nt], al[mt], bq);
            }
        }
        if (c < NCH - 1) {
            sts((c + 1) & 1);
            if (c < NCH - 2) ldg(c + 2);
        }
        __syncthreads();
    }

    const int g  = lane >> 2;
    const int t2 = (lane & 3) * 2;
#pragma unroll
    for (int mt = 0; mt < 2; ++mt) {
#pragma unroll
        for (int nt = 0; nt < 8; ++nt) {
            const int r0 = m0 + wm + mt * 16 + g;
            const int c0 = n0 + wn + nt * 8 + t2;
            *reinterpret_cast<float2*>(C + (size_t)r0 * DIMK + c0) =
                make_float2(acc[mt][nt][0], acc[mt][nt][1]);
            *reinterpret_cast<float2*>(C + (size_t)(r0 + 8) * DIMK + c0) =
                make_float2(acc[mt][nt][2], acc[mt][nt][3]);
        }
    }
}

// ---------------------------------------------------------------------------
// Prep kernels (fragment-layout writers)
// ---------------------------------------------------------------------------
// x -> A-frag: grid (6, 1024) x2 halves, block 256; warp w handles s=bx*8+w
__global__ __launch_bounds__(256) void prep_xa(const float* __restrict__ x,
                                               int mb_off)
{
    const int mblk = mb_off + blockIdx.y;
    const int s    = blockIdx.x * 8 + (threadIdx.x >> 5);
    const int lane = threadIdx.x & 31;
    const int r = mblk * 16 + (lane >> 2);
    const int c = s * 16 + (lane & 3) * 2;
    const float* xr0 = x + (size_t)r * DIMK + c;
    const float* xr1 = x + (size_t)(r + 8) * DIMK + c;
    float2 v0 = *reinterpret_cast<const float2*>(xr0);
    float2 v1 = *reinterpret_cast<const float2*>(xr1);
    float2 v2 = *reinterpret_cast<const float2*>(xr0 + 8);
    float2 v3 = *reinterpret_cast<const float2*>(xr1 + 8);
    g_xa[((size_t)mblk * NK16 + s) * 32 + lane] =
        make_uint4(pack2f(v0.x, v0.y), pack2f(v1.x, v1.y),
                   pack2f(v2.x, v2.y), pack2f(v3.x, v3.y));
}

// W [k][n] fp32 -> B-frag; grid (6, 48, slot? no: slot arg), block 256
// R11 FIX: select destination INSIDE device code (host-side __device__
// symbol addresses are host-shadow addresses -> silent wrong writes).
__global__ __launch_bounds__(256) void prep_wf(const float* __restrict__ W,
                                               int slot)
{
    uint4* __restrict__ dst = slot ? g_wf1 : g_wf0;
    const int p    = blockIdx.y;                    // n-pair (16 rows)
    const int s    = blockIdx.x * 8 + (threadIdx.x >> 5);
    const int lane = threadIdx.x & 31;
    const int nA = p * 16 + (lane >> 2);
    const int nB = nA + 8;
    const int k0 = s * 16 + (lane & 3) * 2;
    const float* Wk0 = W + (size_t)k0 * DIMK;
    uint32_t w0 = pack2f(Wk0[nA],            Wk0[DIMK + nA]);
    uint32_t w1 = pack2f(Wk0[8 * DIMK + nA], Wk0[9 * DIMK + nA]);
    uint32_t w2 = pack2f(Wk0[nB],            Wk0[DIMK + nB]);
    uint32_t w3 = pack2f(Wk0[8 * DIMK + nB], Wk0[9 * DIMK + nB]);
    dst[((size_t)p * NK16 + s) * 32 + lane] = make_uint4(w0, w1, w2, w3);
}

// Wr -> g_wtr ([n][k] row-major fp16) for compose
__global__ __launch_bounds__(256) void prep_wtr(const float* __restrict__ Wr)
{
    const int n = blockIdx.x;
    __half* dst = g_wtr + (size_t)n * DIMK;
    for (int k = threadIdx.x; k < DIMK; k += 256)
        dst[k] = __float2half_rn(Wr[(size_t)k * DIMK + n]);
}

// (g_wc[b] + Wq) [i][e] fp32 -> B-frag (n=e rows, k=i); grid (6, 48, 8)
__global__ __launch_bounds__(256) void prep_bcf(const float* __restrict__ Wq)
{
    const int b    = blockIdx.z;
    const int p    = blockIdx.y;
    const int s    = blockIdx.x * 8 + (threadIdx.x >> 5);
    const int lane = threadIdx.x & 31;
    const float* Wc = g_wc + (size_t)b * WELEM;
    const int eA = p * 16 + (lane >> 2);
    const int eB = eA + 8;
    const int i0 = s * 16 + (lane & 3) * 2;
    const size_t r0 = (size_t)i0 * DIMK;
    uint32_t w0 = pack2f(Wc[r0 + eA] + Wq[r0 + eA],
                         Wc[r0 + DIMK + eA] + Wq[r0 + DIMK + eA]);
    uint32_t w1 = pack2f(Wc[r0 + 8 * DIMK + eA] + Wq[r0 + 8 * DIMK + eA],
                         Wc[r0 + 9 * DIMK + eA] + Wq[r0 + 9 * DIMK + eA]);
    uint32_t w2 = pack2f(Wc[r0 + eB] + Wq[r0 + eB],
                         Wc[r0 + DIMK + eB] + Wq[r0 + DIMK + eB]);
    uint32_t w3 = pack2f(Wc[r0 + 8 * DIMK + eB] + Wq[r0 + 8 * DIMK + eB],
                         Wc[r0 + 9 * DIMK + eB] + Wq[r0 + 9 * DIMK + eB]);
    g_bcf[(size_t)b * BFRAG_N + ((size_t)p * NK16 + s) * 32 + lane] =
        make_uint4(w0, w1, w2, w3);
}

// ---------------------------------------------------------------------------
// Phase kernels (deterministic two-stage reductions)
// ---------------------------------------------------------------------------
#define LOG2E 1.4426950408889634f
#define SCALE 0.03608439182435161f   // 768^-0.5

__global__ __launch_bounds__(256, 2) void phase_kernel(
    const float* __restrict__ coef, int phase)
{
    __shared__ float s_cs[DIMK];
    __shared__ float s_g[DIMK];
    __shared__ float s_acc[8][DIMK];

    const int tid  = threadIdx.x;
    const int lane = tid & 31;
    const int w    = tid >> 5;
    const int blk  = blockIdx.x;
    const int b    = blk / BLKS_PER_BATCH;
    const int r0   = b * NN + (blk % BLKS_PER_BATCH) * ROWS_PER_BLK;

    const float* __restrict__ in = (phase == 0) ? g_q : g_k;

    for (int d = tid; d < DIMK; d += 256) {
        s_cs[d] = coef[d] * SCALE;
        s_g[d]  = (phase == 0) ? 1.f : g_gq[b * DIMK + d];
    }
    __syncthreads();

    float acc[24];
#pragma unroll
    for (int i = 0; i < 24; i++) acc[i] = 0.f;

    for (int rr = w; rr < ROWS_PER_BLK; rr += 8) {
        const float* rp = in + (size_t)(r0 + rr) * DIMK;
        float val[24];
        float m = -1e30f;
#pragma unroll
        for (int i = 0; i < 24; i++) {
            const int d = lane + 32 * i;
            val[i] = rp[d] * s_g[d];
            m = fmaxf(m, val[i] * s_cs[d]);
        }
#pragma unroll
        for (int o = 16; o > 0; o >>= 1)
            m = fmaxf(m, __shfl_xor_sync(0xffffffffu, m, o));
        float sum = 0.f;
#pragma unroll
        for (int i = 0; i < 24; i++) {
            const int d = lane + 32 * i;
            const float e = exp2f((val[i] * s_cs[d] - m) * LOG2E);
            sum += e;
            val[i] *= e;
        }
#pragma unroll
        for (int o = 16; o > 0; o >>= 1)
            sum += __shfl_xor_sync(0xffffffffu, sum, o);
        const float inv = 1.f / sum;
#pragma unroll
        for (int i = 0; i < 24; i++)
            acc[i] = fmaf(val[i], inv, acc[i]);
    }

#pragma unroll
    for (int i = 0; i < 24; i++) s_acc[w][lane + 32 * i] = acc[i];
    __syncthreads();

    for (int d = tid; d < DIMK; d += 256) {
        float s = 0.f;
#pragma unroll
        for (int ww = 0; ww < 8; ww++) s += s_acc[ww][d];
        g_part[(size_t)blk * DIMK + d] = s;
    }
}

// grid (8, 6), block 128
__global__ void reduce_kernel(int phase)
{
    const int b = blockIdx.x;
    const int d = blockIdx.y * 128 + threadIdx.x;
    const float* P = g_part + (size_t)b * BLKS_PER_BATCH * DIMK + d;
    float s0 = 0.f, s1 = 0.f, s2 = 0.f, s3 = 0.f;
#pragma unroll 4
    for (int i = 0; i < BLKS_PER_BATCH; i += 4) {
        s0 += P[(size_t)(i + 0) * DIMK];
        s1 += P[(size_t)(i + 1) * DIMK];
        s2 += P[(size_t)(i + 2) * DIMK];
        s3 += P[(size_t)(i + 3) * DIMK];
    }
    const float s = (s0 + s1) + (s2 + s3);
    if (phase == 0) g_gq[b * DIMK + d] = s;
    else            g_gk[b * DIMK + d] = s;
}

// ---------------------------------------------------------------------------
extern "C" void kernel_launch(void* const* d_in, const int* in_sizes, int n_in,
                              void* d_out, int out_size)
{
    const float* x     = (const float*)d_in[0];
    const float* Wq    = (const float*)d_in[1];
    const float* Wk    = (const float*)d_in[2];
    const float* Wv    = (const float*)d_in[3];
    const float* Wr    = (const float*)d_in[4];
    const float* alpha = (const float*)d_in[5];
    const float* beta  = (const float*)d_in[6];
    float* out = (float*)d_out;

    prep_wf<<<dim3(6, 48), 256>>>(Wq, 0);                 // #1
    prep_wf<<<dim3(6, 48), 256>>>(Wk, 1);                 // #2
    prep_wtr<<<DIMK, 256>>>(Wr);                          // #3
    prep_xa<<<dim3(6, 1024), 256>>>(x, 0);                // #4
    prep_xa<<<dim3(6, 1024), 256>>>(x, 1024);             // #5
    gemm_qk<<<dim3(12, 256), 256>>>();                    // #6 <- ncu -s5 -c1
    phase_kernel<<<NPART, 256>>>(alpha, 0);               // #7
    reduce_kernel<<<dim3(BB, 6), 128>>>(0);               // #8
    phase_kernel<<<NPART, 256>>>(beta, 1);                // #9
    reduce_kernel<<<dim3(BB, 6), 128>>>(1);               // #10
    gemm_compose<<<dim3(6, 6, BB), 256>>>(Wv);            // #11
    prep_bcf<<<dim3(6, 48, BB), 256>>>(Wq);               // #12
    gemm_out<<<dim3(6, 256), 256>>>(out);                 // #13
}

// round 12
// speedup vs baseline: 7.7576x; 1.1278x over previous
#include <cuda_runtime.h>
#include <cuda_fp16.h>
#include <cstdint>

// ---------------------------------------------------------------------------
// Problem constants
// ---------------------------------------------------------------------------
#define BB   8
#define NN   4096
#define DIMK 768
#define MTOT (BB * NN)                   // 32768
#define NELEM ((size_t)MTOT * DIMK)      // 25.2M
#define WELEM (DIMK * DIMK)              // 589824
#define NK16  (DIMK / 16)                // 48 k16 steps

// ---------------------------------------------------------------------------
// Scratch (device globals; no allocation allowed)
// ---------------------------------------------------------------------------
__device__ __half g_qh[NELEM];           // q (fp16; feeds phase 0 only)
__device__ __half g_kh[NELEM];           // k (fp16; feeds phase 1 only)
__device__ float g_gq[BB * DIMK];
__device__ float g_gk[BB * DIMK];
__device__ float g_wc[BB * WELEM];       // composed Wv*diag(gk_b)*Wr (fp32)

#define ROWS_PER_BLK 32
#define BLKS_PER_BATCH (NN / ROWS_PER_BLK)   // 128
#define NPART (BB * BLKS_PER_BATCH)          // 1024
__device__ float g_part[(size_t)NPART * DIMK];

// Fragment-layout operands (uint4 = 16B per lane per k16 step)
//   A frag: [mblk(16 rows)][s(48)][lane(32)] -> words a0,a1,a2,a3
//   B frag: [npair(16 rows)][s(48)][lane(32)] -> words w0..w3
#define AFRAG_N ((size_t)(MTOT / 16) * NK16 * 32)     // 3.15M uint4
#define BFRAG_N ((size_t)(DIMK / 16) * NK16 * 32)     // 73728 uint4
__device__ uint4 g_xa[AFRAG_N];                  // x in A-frag layout (fp16)
__device__ uint4 g_wfa[3][BFRAG_N];              // Wq / Wk / Wr B-frags
__device__ uint4 g_avf[BB * BFRAG_N];            // gk_b ⊙ Wv A-frags (768 rows)
__device__ uint4 g_bcf[BB * BFRAG_N];            // (Wq + Wc_b) B-frag

// ---------------------------------------------------------------------------
// mma.sync (fp16 in, fp32 accum)
// ---------------------------------------------------------------------------
#define MMA16816F16(d, a, b) \
    asm volatile("mma.sync.aligned.m16n8k16.row.col.f32.f16.f16.f32 " \
        "{%0,%1,%2,%3},{%4,%5,%6,%7},{%8,%9},{%0,%1,%2,%3};" \
        : "+f"((d)[0]), "+f"((d)[1]), "+f"((d)[2]), "+f"((d)[3]) \
        : "r"((a)[0]), "r"((a)[1]), "r"((a)[2]), "r"((a)[3]), \
          "r"((b)[0]), "r"((b)[1]))

__device__ __forceinline__ uint32_t pack2h(__half a, __half b) {
    return (uint32_t)__half_as_ushort(a) |
           ((uint32_t)__half_as_ushort(b) << 16);
}
__device__ __forceinline__ uint32_t pack2f(float a, float b) {
    return pack2h(__float2half_rn(a), __float2half_rn(b));
}

// epilogue store helpers (fp32 vs fp16 destination)
__device__ __forceinline__ void store2(float* C, size_t off, float a, float b) {
    *reinterpret_cast<float2*>(C + off) = make_float2(a, b);
}
__device__ __forceinline__ void store2(__half* C, size_t off, float a, float b) {
    *reinterpret_cast<__half2*>(C + off) = __floats2half2_rn(a, b);
}

// ===========================================================================
// SMEM-FREE fp16 GEMM: C[M,768] = A @ B^T, operands in fragment layout.
// CTA tile 128x128, 8 warps (4m x 2n), warp tile 32x64.
// Per k16 step per warp: 2 A-LDG.128 + 4 B-LDG.128 + 16 HMMA; register
// double buffer, no shared memory, no barriers in the mainloop.
// ===========================================================================
#define STEP32 32                       // uint4 stride between k16 steps
#define BLKOFF (NK16 * 32)              // 1536: uint4 stride between m/n blocks

template<typename T>
__device__ __forceinline__ void gemm_frag(
    const uint4* __restrict__ Afrag,
    const uint4* __restrict__ Bfrag,
    T* __restrict__ C, int m0, int n0)
{
    const int tid  = threadIdx.x;
    const int wid  = tid >> 5;
    const int lane = tid & 31;
    const int wm = (wid & 3) * 32;
    const int wn = (wid >> 2) * 64;

    const uint4* pa = Afrag + (size_t)((m0 + wm) >> 4) * BLKOFF + lane;
    const uint4* pb = Bfrag + (size_t)((n0 + wn) >> 4) * BLKOFF + lane;

    float acc[2][8][4];
#pragma unroll
    for (int i = 0; i < 2; i++)
#pragma unroll
        for (int j = 0; j < 8; j++)
#pragma unroll
            for (int l = 0; l < 4; l++) acc[i][j][l] = 0.f;

    uint4 a0[2], a1[2];        // [mt]
    uint4 b0[4], b1[4];        // [npair]

    a0[0] = pa[0]; a0[1] = pa[BLKOFF];
    b0[0] = pb[0];          b0[1] = pb[BLKOFF];
    b0[2] = pb[2 * BLKOFF]; b0[3] = pb[3 * BLKOFF];
    pa += STEP32; pb += STEP32;

    auto step = [&](uint4 (&ac)[2], uint4 (&bc)[4],
                    uint4 (&an)[2], uint4 (&bn)[4], bool pf) {
        if (pf) {
            an[0] = pa[0]; an[1] = pa[BLKOFF];
            bn[0] = pb[0];          bn[1] = pb[BLKOFF];
            bn[2] = pb[2 * BLKOFF]; bn[3] = pb[3 * BLKOFF];
            pa += STEP32; pb += STEP32;
        }
        const uint32_t* am0 = reinterpret_cast<const uint32_t*>(&ac[0]);
        const uint32_t* am1 = reinterpret_cast<const uint32_t*>(&ac[1]);
#pragma unroll
        for (int pr = 0; pr < 4; ++pr) {
            const uint32_t* bw = reinterpret_cast<const uint32_t*>(&bc[pr]);
            MMA16816F16(acc[0][2 * pr],     am0, bw);
            MMA16816F16(acc[1][2 * pr],     am1, bw);
            MMA16816F16(acc[0][2 * pr + 1], am0, bw + 2);
            MMA16816F16(acc[1][2 * pr + 1], am1, bw + 2);
        }
    };

#pragma unroll 1
    for (int s = 0; s < NK16; s += 2) {
        step(a0, b0, a1, b1, true);              // compute s, prefetch s+1
        step(a1, b1, a0, b0, s + 2 < NK16);      // compute s+1, prefetch s+2
    }

    const int g  = lane >> 2;
    const int t2 = (lane & 3) * 2;
#pragma unroll
    for (int mt = 0; mt < 2; ++mt) {
#pragma unroll
        for (int nt = 0; nt < 8; ++nt) {
            const int r0 = m0 + wm + mt * 16 + g;
            const int c0 = n0 + wn + nt * 8 + t2;
            store2(C, (size_t)r0 * DIMK + c0,       acc[mt][nt][0], acc[mt][nt][1]);
            store2(C, (size_t)(r0 + 8) * DIMK + c0, acc[mt][nt][2], acc[mt][nt][3]);
        }
    }
}

// fused q|k: grid (12, 256); x-halves select weight + destination (fp16 out)
__global__ __launch_bounds__(256, 2) void gemm_qk()
{
    const int bx = blockIdx.x;
    const bool sel = bx >= 6;
    gemm_frag<__half>(g_xa, sel ? g_wfa[1] : g_wfa[0], sel ? g_kh : g_qh,
                      blockIdx.y * 128, (sel ? bx - 6 : bx) * 128);
}
// Wc_b = (gk_b ⊙ Wv) @ Wr : grid (6, 6, 8), fragment path
__global__ __launch_bounds__(256, 2) void gemm_compose()
{
    const int b = blockIdx.z;
    gemm_frag<float>(g_avf + (size_t)b * BFRAG_N, g_wfa[2],
                     g_wc + (size_t)b * WELEM,
                     blockIdx.y * 128, blockIdx.x * 128);
}
// out_b = x_b @ (Wq + Wc_b)^T : grid (6, 256)
__global__ __launch_bounds__(256, 2) void gemm_out(float* __restrict__ out)
{
    const int m0 = blockIdx.y * 128;
    const int b  = m0 >> 12;
    gemm_frag<float>(g_xa, g_bcf + (size_t)b * BFRAG_N, out, m0, blockIdx.x * 128);
}

// ---------------------------------------------------------------------------
// Prep kernels (fragment-layout writers; dst selected in DEVICE code)
// ---------------------------------------------------------------------------
// x -> A-frag: grid (6, 2048), block 256; warp w handles s = bx*8 + w
__global__ __launch_bounds__(256) void prep_xa(const float* __restrict__ x)
{
    const int mblk = blockIdx.y;
    const int s    = blockIdx.x * 8 + (threadIdx.x >> 5);
    const int lane = threadIdx.x & 31;
    const int r = mblk * 16 + (lane >> 2);
    const int c = s * 16 + (lane & 3) * 2;
    const float* xr0 = x + (size_t)r * DIMK + c;
    const float* xr1 = x + (size_t)(r + 8) * DIMK + c;
    float2 v0 = *reinterpret_cast<const float2*>(xr0);
    float2 v1 = *reinterpret_cast<const float2*>(xr1);
    float2 v2 = *reinterpret_cast<const float2*>(xr0 + 8);
    float2 v3 = *reinterpret_cast<const float2*>(xr1 + 8);
    g_xa[((size_t)mblk * NK16 + s) * 32 + lane] =
        make_uint4(pack2f(v0.x, v0.y), pack2f(v1.x, v1.y),
                   pack2f(v2.x, v2.y), pack2f(v3.x, v3.y));
}

// W [k][n] fp32 -> B-frag slot; grid (6, 48), block 256
__global__ __launch_bounds__(256) void prep_wf(const float* __restrict__ W,
                                               int slot)
{
    uint4* __restrict__ dst = g_wfa[slot];
    const int p    = blockIdx.y;                    // n-pair (16 rows)
    const int s    = blockIdx.x * 8 + (threadIdx.x >> 5);
    const int lane = threadIdx.x & 31;
    const int nA = p * 16 + (lane >> 2);
    const int nB = nA + 8;
    const int k0 = s * 16 + (lane & 3) * 2;
    const float* Wk0 = W + (size_t)k0 * DIMK;
    uint32_t w0 = pack2f(Wk0[nA],            Wk0[DIMK + nA]);
    uint32_t w1 = pack2f(Wk0[8 * DIMK + nA], Wk0[9 * DIMK + nA]);
    uint32_t w2 = pack2f(Wk0[nB],            Wk0[DIMK + nB]);
    uint32_t w3 = pack2f(Wk0[8 * DIMK + nB], Wk0[9 * DIMK + nB]);
    dst[((size_t)p * NK16 + s) * 32 + lane] = make_uint4(w0, w1, w2, w3);
}

// (gk_b ⊙ Wv) -> per-batch A-frag; grid (6, 48, 8)
__global__ __launch_bounds__(256) void prep_av(const float* __restrict__ Wv)
{
    const int b    = blockIdx.z;
    const int mblk = blockIdx.y;
    const int s    = blockIdx.x * 8 + (threadIdx.x >> 5);
    const int lane = threadIdx.x & 31;
    const int r = mblk * 16 + (lane >> 2);
    const int c = s * 16 + (lane & 3) * 2;
    const float* gk = g_gk + b * DIMK;
    const float s0 = gk[c], s1 = gk[c + 1], s2 = gk[c + 8], s3 = gk[c + 9];
    const float* wr0 = Wv + (size_t)r * DIMK + c;
    const float* wr1 = Wv + (size_t)(r + 8) * DIMK + c;
    float2 v0 = *reinterpret_cast<const float2*>(wr0);
    float2 v1 = *reinterpret_cast<const float2*>(wr1);
    float2 v2 = *reinterpret_cast<const float2*>(wr0 + 8);
    float2 v3 = *reinterpret_cast<const float2*>(wr1 + 8);
    g_avf[(size_t)b * BFRAG_N + ((size_t)mblk * NK16 + s) * 32 + lane] =
        make_uint4(pack2f(v0.x * s0, v0.y * s1), pack2f(v1.x * s0, v1.y * s1),
                   pack2f(v2.x * s2, v2.y * s3), pack2f(v3.x * s2, v3.y * s3));
}

// (g_wc[b] + Wq) [i][e] fp32 -> B-frag (n=e rows, k=i); grid (6, 48, 8)
__global__ __launch_bounds__(256) void prep_bcf(const float* __restrict__ Wq)
{
    const int b    = blockIdx.z;
    const int p    = blockIdx.y;
    const int s    = blockIdx.x * 8 + (threadIdx.x >> 5);
    const int lane = threadIdx.x & 31;
    const float* Wc = g_wc + (size_t)b * WELEM;
    const int eA = p * 16 + (lane >> 2);
    const int eB = eA + 8;
    const int i0 = s * 16 + (lane & 3) * 2;
    const size_t r0 = (size_t)i0 * DIMK;
    uint32_t w0 = pack2f(Wc[r0 + eA] + Wq[r0 + eA],
                         Wc[r0 + DIMK + eA] + Wq[r0 + DIMK + eA]);
    uint32_t w1 = pack2f(Wc[r0 + 8 * DIMK + eA] + Wq[r0 + 8 * DIMK + eA],
                         Wc[r0 + 9 * DIMK + eA] + Wq[r0 + 9 * DIMK + eA]);
    uint32_t w2 = pack2f(Wc[r0 + eB] + Wq[r0 + eB],
                         Wc[r0 + DIMK + eB] + Wq[r0 + DIMK + eB]);
    uint32_t w3 = pack2f(Wc[r0 + 8 * DIMK + eB] + Wq[r0 + 8 * DIMK + eB],
                         Wc[r0 + 9 * DIMK + eB] + Wq[r0 + 9 * DIMK + eB]);
    g_bcf[(size_t)b * BFRAG_N + ((size_t)p * NK16 + s) * 32 + lane] =
        make_uint4(w0, w1, w2, w3);
}

// ---------------------------------------------------------------------------
// Phase kernels (deterministic two-stage reductions; fp16 q/k inputs)
// ---------------------------------------------------------------------------
#define LOG2E 1.4426950408889634f
#define SCALE 0.03608439182435161f   // 768^-0.5

__global__ __launch_bounds__(256, 2) void phase_kernel(
    const float* __restrict__ coef, int phase)
{
    __shared__ float2 s_cs[DIMK / 2];     // (coef*SCALE) pairs
    __shared__ float2 s_g[DIMK / 2];
    __shared__ float2 s_acc[8][DIMK / 2];

    const int tid  = threadIdx.x;
    const int lane = tid & 31;
    const int w    = tid >> 5;
    const int blk  = blockIdx.x;
    const int b    = blk / BLKS_PER_BATCH;
    const int r0   = b * NN + (blk % BLKS_PER_BATCH) * ROWS_PER_BLK;

    const __half* __restrict__ in = (phase == 0) ? g_qh : g_kh;

    for (int d = tid; d < DIMK / 2; d += 256) {
        s_cs[d] = make_float2(coef[2 * d] * SCALE, coef[2 * d + 1] * SCALE);
        s_g[d]  = (phase == 0)
            ? make_float2(1.f, 1.f)
            : make_float2(g_gq[b * DIMK + 2 * d], g_gq[b * DIMK + 2 * d + 1]);
    }
    __syncthreads();

    float acc[24];
#pragma unroll
    for (int i = 0; i < 24; i++) acc[i] = 0.f;

    for (int rr = w; rr < ROWS_PER_BLK; rr += 8) {
        const __half2* rp = reinterpret_cast<const __half2*>(
            in + (size_t)(r0 + rr) * DIMK);
        float val[24];
        float m = -1e30f;
#pragma unroll
        for (int i = 0; i < 12; i++) {
            const int dp = lane + 32 * i;
            const float2 v  = __half22float2(rp[dp]);
            const float2 gg = s_g[dp];
            const float2 cs = s_cs[dp];
            val[2 * i]     = v.x * gg.x;
            val[2 * i + 1] = v.y * gg.y;
            m = fmaxf(m, val[2 * i] * cs.x);
            m = fmaxf(m, val[2 * i + 1] * cs.y);
        }
#pragma unroll
        for (int o = 16; o > 0; o >>= 1)
            m = fmaxf(m, __shfl_xor_sync(0xffffffffu, m, o));
        float sum = 0.f;
#pragma unroll
        for (int i = 0; i < 12; i++) {
            const int dp = lane + 32 * i;
            const float2 cs = s_cs[dp];
            const float e0 = exp2f((val[2 * i] * cs.x - m) * LOG2E);
            const float e1 = exp2f((val[2 * i + 1] * cs.y - m) * LOG2E);
            sum += e0 + e1;
            val[2 * i]     *= e0;
            val[2 * i + 1] *= e1;
        }
#pragma unroll
        for (int o = 16; o > 0; o >>= 1)
            sum += __shfl_xor_sync(0xffffffffu, sum, o);
        const float inv = 1.f / sum;
#pragma unroll
        for (int i = 0; i < 24; i++)
            acc[i] = fmaf(val[i], inv, acc[i]);
    }

#pragma unroll
    for (int i = 0; i < 12; i++)
        s_acc[w][lane + 32 * i] = make_float2(acc[2 * i], acc[2 * i + 1]);
    __syncthreads();

    float2* P = reinterpret_cast<float2*>(g_part + (size_t)blk * DIMK);
    for (int d = tid; d < DIMK / 2; d += 256) {
        float sx = 0.f, sy = 0.f;
#pragma unroll
        for (int ww = 0; ww < 8; ww++) {
            const float2 t = s_acc[ww][d];
            sx += t.x; sy += t.y;
        }
        P[d] = make_float2(sx, sy);
    }
}

// grid (8, 6), block 128
__global__ void reduce_kernel(int phase)
{
    const int b = blockIdx.x;
    const int d = blockIdx.y * 128 + threadIdx.x;
    const float* P = g_part + (size_t)b * BLKS_PER_BATCH * DIMK + d;
    float s0 = 0.f, s1 = 0.f, s2 = 0.f, s3 = 0.f;
#pragma unroll 4
    for (int i = 0; i < BLKS_PER_BATCH; i += 4) {
        s0 += P[(size_t)(i + 0) * DIMK];
        s1 += P[(size_t)(i + 1) * DIMK];
        s2 += P[(size_t)(i + 2) * DIMK];
        s3 += P[(size_t)(i + 3) * DIMK];
    }
    const float s = (s0 + s1) + (s2 + s3);
    if (phase == 0) g_gq[b * DIMK + d] = s;
    else            g_gk[b * DIMK + d] = s;
}

// ---------------------------------------------------------------------------
extern "C" void kernel_launch(void* const* d_in, const int* in_sizes, int n_in,
                              void* d_out, int out_size)
{
    const float* x     = (const float*)d_in[0];
    const float* Wq    = (const float*)d_in[1];
    const float* Wk    = (const float*)d_in[2];
    const float* Wv    = (const float*)d_in[3];
    const float* Wr    = (const float*)d_in[4];
    const float* alpha = (const float*)d_in[5];
    const float* beta  = (const float*)d_in[6];
    float* out = (float*)d_out;

    prep_wf<<<dim3(6, 48), 256>>>(Wq, 0);                 // #1
    prep_wf<<<dim3(6, 48), 256>>>(Wk, 1);                 // #2
    prep_wf<<<dim3(6, 48), 256>>>(Wr, 2);                 // #3
    prep_xa<<<dim3(6, 2048), 256>>>(x);                   // #4
    gemm_qk<<<dim3(12, 256), 256>>>();                    // #5
    phase_kernel<<<NPART, 256>>>(alpha, 0);               // #6  <- ncu -s5 -c1
    reduce_kernel<<<dim3(BB, 6), 128>>>(0);               // #7
    phase_kernel<<<NPART, 256>>>(beta, 1);                // #8
    reduce_kernel<<<dim3(BB, 6), 128>>>(1);               // #9
    prep_av<<<dim3(6, 48, BB), 256>>>(Wv);                // #10
    gemm_compose<<<dim3(6, 6, BB), 256>>>();              // #11
    prep_bcf<<<dim3(6, 48, BB), 256>>>(Wq);               // #12
    gemm_out<<<dim3(6, 256), 256>>>(out);                 // #13
}